// round 11
// baseline (speedup 1.0000x reference)
#include <cuda_runtime.h>
#include <cuda_bf16.h>
#include <math.h>
#include <stdint.h>

// ---------------- problem constants ----------------
#define NN     100000      // nodes
#define EE     1600000     // edges
#define NH     4           // heads
#define FN     32
#define FE     16
#define HFN    128         // NH*FN
#define HFE    64          // NH*FE

// ---------------- scratch (device globals) ----------------
__device__ float g_fni [NN * HFE];
__device__ float g_fnj [NN * HFE];
__device__ float g_h   [NN * HFN];
__device__ float g_eexp[EE * NH];      // original edge order
__device__ int   g_cnt [NN];
__device__ int   g_rowoff[NN + 1];
__device__ int   g_bsum[128];
__device__ int   g_perm[EE];           // CSR position -> original edge id
__device__ int   g_psrc[EE];           // src in CSR order

// ================= helpers =================
__device__ __forceinline__ uint32_t smem_u32(const void* p) {
    uint32_t r;
    asm("{ .reg .u64 t; cvta.to.shared.u64 t, %1; cvt.u32.u64 %0, t; }"
        : "=r"(r) : "l"(p));
    return r;
}
// cutlass Swizzle<3,4,3>: conflict-free ldmatrix on 128B-row atoms
#define SWZ(x) ((x) ^ (((x) >> 3) & 0x70))

#define LDSM4(r0, r1, r2, r3, a) \
    asm volatile("ldmatrix.sync.aligned.m8n8.x4.shared.b16 {%0,%1,%2,%3}, [%4];" \
                 : "=r"(r0), "=r"(r1), "=r"(r2), "=r"(r3) : "r"(a))

#define MMA16816(d, a, b0, b1) \
    asm volatile("mma.sync.aligned.m16n8k16.row.col.f32.bf16.bf16.f32 " \
                 "{%0,%1,%2,%3},{%4,%5,%6,%7},{%8,%9},{%0,%1,%2,%3};" \
                 : "+f"((d)[0]), "+f"((d)[1]), "+f"((d)[2]), "+f"((d)[3]) \
                 : "r"((a)[0]), "r"((a)[1]), "r"((a)[2]), "r"((a)[3]), \
                   "r"(b0), "r"(b1))

// packed bf16 two-term split of (x,y):
//   hi = {bf16(y) : bf16(x)}, lo = {bf16(y - hi_y) : bf16(x - hi_x)}
__device__ __forceinline__ void split2pack(float x, float y, uint32_t& hi, uint32_t& lo) {
    asm("cvt.rn.bf16x2.f32 %0, %1, %2;" : "=r"(hi) : "f"(y), "f"(x));
    float hx = __uint_as_float(hi << 16);
    float hy = __uint_as_float(hi & 0xFFFF0000u);
    float rx = x - hx;
    float ry = y - hy;
    asm("cvt.rn.bf16x2.f32 %0, %1, %2;" : "=r"(lo) : "f"(ry), "f"(rx));
}
// scalar split (weights staging only; negligible volume)
__device__ __forceinline__ void split_bf(float x, unsigned short& h, unsigned short& l) {
    __nv_bfloat16 bh = __float2bfloat16_rn(x);
    h = __bfloat16_as_ushort(bh);
    float r = x - __bfloat162float(bh);
    l = __bfloat16_as_ushort(__float2bfloat16_rn(r));
}

// ================= CSR build =================
__global__ void zero_cnt_kernel() {
    int i = blockIdx.x * blockDim.x + threadIdx.x;
    if (i < NN) g_cnt[i] = 0;
}
__global__ void deg_kernel(const int* __restrict__ dst) {
    int e = blockIdx.x * blockDim.x + threadIdx.x;
    if (e < EE) atomicAdd(&g_cnt[dst[e]], 1);
}

// multi-block scan: local block scans + block-sum scan + fixup
#define SCAN_B ((NN + 1023) / 1024)      // 98
__global__ void scan1_kernel() {
    __shared__ int wsums[32];
    int tid = threadIdx.x, lane = tid & 31, wid = tid >> 5;
    int i = blockIdx.x * 1024 + tid;
    int v = (i < NN) ? g_cnt[i] : 0;
    int x = v;
    #pragma unroll
    for (int o = 1; o < 32; o <<= 1) {
        int y = __shfl_up_sync(0xffffffffu, x, o);
        if (lane >= o) x += y;
    }
    if (lane == 31) wsums[wid] = x;
    __syncthreads();
    if (wid == 0) {
        int s = wsums[lane];
        #pragma unroll
        for (int o = 1; o < 32; o <<= 1) {
            int y = __shfl_up_sync(0xffffffffu, s, o);
            if (lane >= o) s += y;
        }
        wsums[lane] = s;
    }
    __syncthreads();
    int warp_off = (wid == 0) ? 0 : wsums[wid - 1];
    int incl = x + warp_off;
    if (i < NN) g_rowoff[i] = incl - v;        // local exclusive
    if (tid == 1023) g_bsum[blockIdx.x] = incl;
}
__global__ void scan2_kernel() {
    __shared__ int ws[4];
    int tid = threadIdx.x, lane = tid & 31, wid = tid >> 5;
    int v = (tid < SCAN_B) ? g_bsum[tid] : 0;
    int x = v;
    #pragma unroll
    for (int o = 1; o < 32; o <<= 1) {
        int y = __shfl_up_sync(0xffffffffu, x, o);
        if (lane >= o) x += y;
    }
    if (lane == 31) ws[wid] = x;
    __syncthreads();
    if (tid == 0) {
        int a = 0;
        #pragma unroll
        for (int k = 0; k < 4; k++) { int t = ws[k]; ws[k] = a; a += t; }
        g_rowoff[NN] = a;
    }
    __syncthreads();
    if (tid < SCAN_B) g_bsum[tid] = x - v + ws[wid];   // exclusive block offset
}
__global__ void scan3_kernel() {
    int i = blockIdx.x * 1024 + threadIdx.x;
    if (i < NN) {
        int r = g_rowoff[i] + g_bsum[blockIdx.x];
        g_rowoff[i] = r;
        g_cnt[i] = r;                       // scatter cursor
    }
}

__global__ void scatter_kernel(const int* __restrict__ src,
                               const int* __restrict__ dst) {
    int e = blockIdx.x * blockDim.x + threadIdx.x;
    if (e < EE) {
        int d = dst[e];
        int pos = atomicAdd(&g_cnt[d], 1);
        g_perm[pos] = e;
        g_psrc[pos] = src[e];
    }
}

// ================= K1: node projections (mma.sync bf16 3-split) =================
// D[128 rows, 256 cols] = A[128,128] @ W^T[256,128]
// cols 0..63 -> g_fni, 64..127 -> g_fnj, 128..255 -> g_h (+bias)
#define K1_TILES ((NN + 127) / 128)    // 782

__global__ void __launch_bounds__(512, 1)
node_proj_mma(const float* __restrict__ nfeats, const float* __restrict__ Wnode,
              const float* __restrict__ bnode, const float* __restrict__ Wni,
              const float* __restrict__ Wnj)
{
    extern __shared__ unsigned char dynbuf[];
    __shared__ float sbias[HFN];

    uint32_t du = smem_u32(dynbuf);
    uint32_t b0a = (du + 1023u) & ~1023u;
    unsigned char* dp = dynbuf + (b0a - du);
    const uint32_t A_HI = 0, A_LO = 32768, B_HI = 65536, B_LO = 131072;

    int tid = threadIdx.x, lane = tid & 31, wid = tid >> 5;
    int mwarp = wid & 3, nwarp = wid >> 2;
    int lm = lane >> 3, lr = lane & 7;

    if (tid < HFN) sbias[tid] = bnode[tid];

    // Stage fused weights [256 n x 128 k], bf16 hi/lo
    for (int idx = tid; idx < 256 * 128; idx += 512) {
        int n = idx & 255, k = idx >> 8;
        float w;
        if (n < 64)        w = Wni[k * 64 + n];
        else if (n < 128)  w = Wnj[k * 64 + (n - 64)];
        else               w = Wnode[k * 128 + (n - 128)];
        unsigned short h, l;
        split_bf(w, h, l);
        uint32_t off = (uint32_t)((n >> 3) + ((k >> 6) << 5)) * 1024u
                     + (uint32_t)(n & 7) * 128u + ((uint32_t)(k & 63) << 1);
        uint32_t so = SWZ(off);
        *(unsigned short*)(dp + B_HI + so) = h;
        *(unsigned short*)(dp + B_LO + so) = l;
    }

    const uint32_t saHI = b0a + A_HI, saLO = b0a + A_LO;
    const uint32_t sbHI = b0a + B_HI, sbLO = b0a + B_LO;

    for (int tile = blockIdx.x; tile < K1_TILES; tile += gridDim.x) {
        int n0 = tile * 128;
        __syncthreads();
        // stage A tile [128 x 128] fp32 -> bf16 hi/lo (packed cvt)
        #pragma unroll
        for (int j = 0; j < 8; j++) {
            int i = j * 512 + tid;          // float4 index 0..4095
            int row = i >> 5;
            int kg  = (i & 31) << 2;
            int n = n0 + row;
            float4 x = make_float4(0.f, 0.f, 0.f, 0.f);
            if (n < NN) x = *(const float4*)&nfeats[(size_t)n * 128 + kg];
            uint32_t h01, l01, h23, l23;
            split2pack(x.x, x.y, h01, l01);
            split2pack(x.z, x.w, h23, l23);
            uint32_t off = (uint32_t)((row >> 3) + ((kg >> 6) << 4)) * 1024u
                         + (uint32_t)(row & 7) * 128u + ((uint32_t)(kg & 63) << 1);
            uint32_t so = SWZ(off);
            *(uint2*)(dp + A_HI + so) = make_uint2(h01, h23);
            *(uint2*)(dp + A_LO + so) = make_uint2(l01, l23);
        }
        __syncthreads();

        float acc[2][8][4];
        #pragma unroll
        for (int mf = 0; mf < 2; mf++)
            #pragma unroll
            for (int nf = 0; nf < 8; nf++)
                #pragma unroll
                for (int q = 0; q < 4; q++) acc[mf][nf][q] = 0.f;

        #pragma unroll
        for (int term = 0; term < 3; term++) {
            uint32_t abase = (term == 2) ? saLO : saHI;
            uint32_t bbase = (term == 1) ? sbLO : sbHI;
            #pragma unroll
            for (int ks = 0; ks < 8; ks++) {
                int k0 = ks * 16;
                uint32_t a[2][4];
                #pragma unroll
                for (int mf = 0; mf < 2; mf++) {
                    int row = mwarp * 32 + mf * 16 + ((lm & 1) << 3) + lr;
                    int kk  = k0 + ((lm >> 1) << 3);
                    uint32_t off = (uint32_t)((row >> 3) + ((kk >> 6) << 4)) * 1024u
                                 + (uint32_t)(row & 7) * 128u + ((uint32_t)(kk & 63) << 1);
                    LDSM4(a[mf][0], a[mf][1], a[mf][2], a[mf][3], abase + SWZ(off));
                }
                uint32_t b[4][4];
                #pragma unroll
                for (int p = 0; p < 4; p++) {
                    int n  = nwarp * 64 + p * 16 + ((lm >> 1) << 3) + lr;
                    int kk = k0 + ((lm & 1) << 3);
                    uint32_t off = (uint32_t)((n >> 3) + ((kk >> 6) << 5)) * 1024u
                                 + (uint32_t)(n & 7) * 128u + ((uint32_t)(kk & 63) << 1);
                    LDSM4(b[p][0], b[p][1], b[p][2], b[p][3], bbase + SWZ(off));
                }
                #pragma unroll
                for (int mf = 0; mf < 2; mf++)
                    #pragma unroll
                    for (int nf = 0; nf < 8; nf++)
                        MMA16816(acc[mf][nf], a[mf],
                                 b[nf >> 1][(nf & 1) * 2], b[nf >> 1][(nf & 1) * 2 + 1]);
            }
        }

        // fragment-layout epilogue
        int rb = n0 + mwarp * 32 + (lane >> 2);
        int cq = (lane & 3) * 2;
        #pragma unroll
        for (int mf = 0; mf < 2; mf++) {
            int r1 = rb + mf * 16, r2 = r1 + 8;
            #pragma unroll
            for (int nf = 0; nf < 8; nf++) {
                int cc = nf * 8 + cq;
                float* a4 = acc[mf][nf];
                float2 v1 = make_float2(a4[0], a4[1]);
                float2 v2 = make_float2(a4[2], a4[3]);
                if (nwarp == 0) {
                    if (r1 < NN) *(float2*)&g_fni[(size_t)r1 * 64 + cc] = v1;
                    if (r2 < NN) *(float2*)&g_fni[(size_t)r2 * 64 + cc] = v2;
                } else if (nwarp == 1) {
                    if (r1 < NN) *(float2*)&g_fnj[(size_t)r1 * 64 + cc] = v1;
                    if (r2 < NN) *(float2*)&g_fnj[(size_t)r2 * 64 + cc] = v2;
                } else {
                    int c2 = (nwarp - 2) * 64 + cc;
                    float b0f = sbias[c2], b1f = sbias[c2 + 1];
                    v1.x += b0f; v1.y += b1f;
                    v2.x += b0f; v2.y += b1f;
                    if (r1 < NN) *(float2*)&g_h[(size_t)r1 * 128 + c2] = v1;
                    if (r2 < NN) *(float2*)&g_h[(size_t)r2 * 128 + c2] = v2;
                }
            }
        }
    }
}

// ================= K2: fused edge kernel (sD overlays A region, 3 CTAs/SM) ===
// After the MMA drains, the 32KB bf16 A region is dead; sD (128x64 fp32 =
// 32KB, XOR-swizzled) reuses it, cutting smem 85KB -> 50KB -> 3 CTAs/SM.
#define K2_TILES (EE / 128)            // 12500, exact

__global__ void __launch_bounds__(256, 3)
edge_mma(const float* __restrict__ efeats, const int* __restrict__ src,
         const int* __restrict__ dst, const float* __restrict__ Wfij,
         const float* __restrict__ attn, const float* __restrict__ bias,
         float* __restrict__ fout)
{
    extern __shared__ unsigned char dynbuf[];
    __shared__ float sattn[HFE], sbias[HFE];

    uint32_t du = smem_u32(dynbuf);
    uint32_t b0a = (du + 1023u) & ~1023u;
    unsigned char* dp = dynbuf + (b0a - du);
    const uint32_t A_HI = 0, A_LO = 16384, B_HI = 32768, B_LO = 40960;
    float* sD = (float*)dp;            // overlays A_HI+A_LO: [128][64] swizzled

    int tid = threadIdx.x, lane = tid & 31, wid = tid >> 5;
    int mwarp = wid & 3, nwarp = wid >> 2;
    int lm = lane >> 3, lr = lane & 7;

    if (tid < HFE) { sattn[tid] = attn[tid]; sbias[tid] = bias[tid]; }

    // Stage Wfij as [n=64][k=64], bf16 hi/lo
    for (int idx = tid; idx < 64 * 64; idx += 256) {
        int n = idx & 63, k = idx >> 6;
        unsigned short h, l;
        split_bf(Wfij[k * 64 + n], h, l);
        uint32_t off = (uint32_t)(n >> 3) * 1024u + (uint32_t)(n & 7) * 128u
                     + ((uint32_t)k << 1);
        uint32_t so = SWZ(off);
        *(unsigned short*)(dp + B_HI + so) = h;
        *(unsigned short*)(dp + B_LO + so) = l;
    }

    const uint32_t saHI = b0a + A_HI, saLO = b0a + A_LO;
    const uint32_t sbHI = b0a + B_HI, sbLO = b0a + B_LO;

    for (int tile = blockIdx.x; tile < K2_TILES; tile += gridDim.x) {
        int e0 = tile * 128;
        __syncthreads();                   // prior tile's sD reads complete
        // stage A tile [128 edges x 64 feats] fp32 -> bf16 hi/lo (packed cvt)
        #pragma unroll
        for (int j = 0; j < 8; j++) {
            int i = j * 256 + tid;          // float4 index 0..2047
            int row = i >> 4;
            int kg  = (i & 15) << 2;
            float4 x = *(const float4*)&efeats[(size_t)(e0 + row) * 64 + kg];
            uint32_t h01, l01, h23, l23;
            split2pack(x.x, x.y, h01, l01);
            split2pack(x.z, x.w, h23, l23);
            uint32_t off = (uint32_t)(row >> 3) * 1024u + (uint32_t)(row & 7) * 128u
                         + ((uint32_t)kg << 1);
            uint32_t so = SWZ(off);
            *(uint2*)(dp + A_HI + so) = make_uint2(h01, h23);
            *(uint2*)(dp + A_LO + so) = make_uint2(l01, l23);
        }
        __syncthreads();

        float acc[2][4][4];
        #pragma unroll
        for (int mf = 0; mf < 2; mf++)
            #pragma unroll
            for (int nf = 0; nf < 4; nf++)
                #pragma unroll
                for (int q = 0; q < 4; q++) acc[mf][nf][q] = 0.f;

        #pragma unroll
        for (int term = 0; term < 3; term++) {
            uint32_t abase = (term == 2) ? saLO : saHI;
            uint32_t bbase = (term == 1) ? sbLO : sbHI;
            #pragma unroll
            for (int ks = 0; ks < 4; ks++) {
                int k0 = ks * 16;
                uint32_t a[2][4];
                #pragma unroll
                for (int mf = 0; mf < 2; mf++) {
                    int row = mwarp * 32 + mf * 16 + ((lm & 1) << 3) + lr;
                    int kk  = k0 + ((lm >> 1) << 3);
                    uint32_t off = (uint32_t)(row >> 3) * 1024u
                                 + (uint32_t)(row & 7) * 128u + ((uint32_t)kk << 1);
                    LDSM4(a[mf][0], a[mf][1], a[mf][2], a[mf][3], abase + SWZ(off));
                }
                uint32_t b[2][4];
                #pragma unroll
                for (int p = 0; p < 2; p++) {
                    int n  = nwarp * 32 + p * 16 + ((lm >> 1) << 3) + lr;
                    int kk = k0 + ((lm & 1) << 3);
                    uint32_t off = (uint32_t)(n >> 3) * 1024u
                                 + (uint32_t)(n & 7) * 128u + ((uint32_t)kk << 1);
                    LDSM4(b[p][0], b[p][1], b[p][2], b[p][3], bbase + SWZ(off));
                }
                #pragma unroll
                for (int mf = 0; mf < 2; mf++)
                    #pragma unroll
                    for (int nf = 0; nf < 4; nf++)
                        MMA16816(acc[mf][nf], a[mf],
                                 b[nf >> 1][(nf & 1) * 2], b[nf >> 1][(nf & 1) * 2 + 1]);
            }
        }

        __syncthreads();                   // all A reads drained before overwrite

        // accumulators -> sD (overlaying A), pitch 64, XOR swizzle on bits 3-4
        {
            int rb = mwarp * 32 + (lane >> 2);
            int cq = (lane & 3) * 2;
            #pragma unroll
            for (int mf = 0; mf < 2; mf++) {
                int r1 = rb + mf * 16, r2 = r1 + 8;
                #pragma unroll
                for (int nf = 0; nf < 4; nf++) {
                    int cc = nwarp * 32 + nf * 8 + cq;
                    float* a4 = acc[mf][nf];
                    int c1 = cc ^ ((r1 & 3) << 3);
                    int c2 = cc ^ ((r2 & 3) << 3);
                    *(float2*)&sD[r1 * 64 + c1] = make_float2(a4[0], a4[1]);
                    *(float2*)&sD[r2 * 64 + c2] = make_float2(a4[2], a4[3]);
                }
            }
        }
        __syncthreads();

        // per-edge epilogue: 2 threads per edge, 32 cols (2 heads) each
        int eloc = tid >> 1;
        int half = tid & 1;
        int e = e0 + eloc;
        int sn = src[e], dn = dst[e];
        const float* fni = &g_fni[(size_t)sn * 64 + half * 32];
        const float* fnj = &g_fnj[(size_t)dn * 64 + half * 32];
        float* fo = &fout[(size_t)e * 64 + half * 32];
        const float* dsm = &sD[eloc * 64 + half * 32];
        int dsw = (eloc & 3) << 3;         // row-dependent XOR (within half)
        float p0 = 0.f, p1 = 0.f;
        #pragma unroll
        for (int g = 0; g < 8; g++) {
            int c = g * 4;
            float4 dd = *(const float4*)&dsm[c ^ dsw];
            float4 a4 = *(const float4*)&fni[c];
            float4 b4 = *(const float4*)&fnj[c];
            int cb = half * 32 + c;
            float4 o;
            o.x = dd.x + a4.x + b4.x + sbias[cb + 0];
            o.y = dd.y + a4.y + b4.y + sbias[cb + 1];
            o.z = dd.z + a4.z + b4.z + sbias[cb + 2];
            o.w = dd.w + a4.w + b4.w + sbias[cb + 3];
            o.x = (o.x > 0.f) ? o.x : 0.01f * o.x;
            o.y = (o.y > 0.f) ? o.y : 0.01f * o.y;
            o.z = (o.z > 0.f) ? o.z : 0.01f * o.z;
            o.w = (o.w > 0.f) ? o.w : 0.01f * o.w;
            float ph = o.x * sattn[cb + 0] + o.y * sattn[cb + 1]
                     + o.z * sattn[cb + 2] + o.w * sattn[cb + 3];
            if (g < 4) p0 += ph; else p1 += ph;
            *(float4*)&fo[c] = o;
        }
        // unnormalized softmax numerators (shift-invariance: segment-max skipped)
        *(float2*)&g_eexp[(size_t)e * 4 + half * 2] =
            make_float2(expf(p0), expf(p1));
    }
}

// ================= K3: per-node aggregation (warp per node, 2x unroll) =================
__global__ void __launch_bounds__(256)
agg_kernel(float* __restrict__ hout)
{
    int warp = (blockIdx.x * blockDim.x + threadIdx.x) >> 5;
    int lane = threadIdx.x & 31;
    if (warp >= NN) return;

    int beg = g_rowoff[warp];
    int end = g_rowoff[warp + 1];

    float a0 = 0.f, a1 = 0.f, a2 = 0.f, a3 = 0.f;
    float s0 = 0.f, s1 = 0.f, s2 = 0.f, s3 = 0.f;

    int i = beg;
    for (; i + 2 <= end; i += 2) {
        int eA = g_perm[i], eB = g_perm[i + 1];
        int sA = g_psrc[i], sB = g_psrc[i + 1];
        float4 exA = *(float4*)&g_eexp[(size_t)eA * 4];
        float4 exB = *(float4*)&g_eexp[(size_t)eB * 4];
        const float* hA = &g_h[(size_t)sA * 128];
        const float* hB = &g_h[(size_t)sB * 128];
        float vA0 = hA[lane],      vB0 = hB[lane];
        float vA1 = hA[32 + lane], vB1 = hB[32 + lane];
        float vA2 = hA[64 + lane], vB2 = hB[64 + lane];
        float vA3 = hA[96 + lane], vB3 = hB[96 + lane];
        a0 = fmaf(exA.x, vA0, a0); a0 = fmaf(exB.x, vB0, a0);
        a1 = fmaf(exA.y, vA1, a1); a1 = fmaf(exB.y, vB1, a1);
        a2 = fmaf(exA.z, vA2, a2); a2 = fmaf(exB.z, vB2, a2);
        a3 = fmaf(exA.w, vA3, a3); a3 = fmaf(exB.w, vB3, a3);
        s0 += exA.x + exB.x; s1 += exA.y + exB.y;
        s2 += exA.z + exB.z; s3 += exA.w + exB.w;
    }
    if (i < end) {
        int e = g_perm[i];
        int s = g_psrc[i];
        float4 ex = *(float4*)&g_eexp[(size_t)e * 4];
        const float* hp = &g_h[(size_t)s * 128];
        a0 = fmaf(ex.x, hp[lane],      a0);
        a1 = fmaf(ex.y, hp[32 + lane], a1);
        a2 = fmaf(ex.z, hp[64 + lane], a2);
        a3 = fmaf(ex.w, hp[96 + lane], a3);
        s0 += ex.x; s1 += ex.y; s2 += ex.z; s3 += ex.w;
    }

    float* op = &hout[(size_t)warp * 128];
    if (end > beg) {
        op[lane]      = a0 / s0;
        op[32 + lane] = a1 / s1;
        op[64 + lane] = a2 / s2;
        op[96 + lane] = a3 / s3;
    } else {
        op[lane] = 0.f; op[32 + lane] = 0.f;
        op[64 + lane] = 0.f; op[96 + lane] = 0.f;
    }
}

// ================= launch =================
extern "C" void kernel_launch(void* const* d_in, const int* in_sizes, int n_in,
                              void* d_out, int out_size)
{
    const float* nfeats = (const float*)d_in[0];
    const float* efeats = (const float*)d_in[1];
    const int*   src    = (const int*)  d_in[2];
    const int*   dst    = (const int*)  d_in[3];
    const float* Wnode  = (const float*)d_in[4];
    const float* bnode  = (const float*)d_in[5];
    const float* Wni    = (const float*)d_in[6];
    const float* Wnj    = (const float*)d_in[7];
    const float* Wfij   = (const float*)d_in[8];
    const float* attn   = (const float*)d_in[9];
    const float* bias   = (const float*)d_in[10];

    float* out  = (float*)d_out;
    float* hout = out;                          // [N*H, FN] = N*128 floats
    float* fout = out + (size_t)NN * HFN;       // [E*H, FE] = E*64 floats

    const int k1_smem = 192 * 1024 + 1024;      // 197632
    const int k2_smem = 48 * 1024 + 1024;       // 50176 (A/sD overlay + B)
    cudaFuncSetAttribute(node_proj_mma,
                         cudaFuncAttributeMaxDynamicSharedMemorySize, k1_smem);
    cudaFuncSetAttribute(edge_mma,
                         cudaFuncAttributeMaxDynamicSharedMemorySize, k2_smem);

    // CSR build (multi-block scan)
    zero_cnt_kernel<<<(NN + 255) / 256, 256>>>();
    deg_kernel<<<(EE + 255) / 256, 256>>>(dst);
    scan1_kernel<<<SCAN_B, 1024>>>();
    scan2_kernel<<<1, 128>>>();
    scan3_kernel<<<SCAN_B, 1024>>>();
    scatter_kernel<<<(EE + 255) / 256, 256>>>(src, dst);

    // tensor-core projections + fused edge pass
    node_proj_mma<<<148, 512, k1_smem>>>(nfeats, Wnode, bnode, Wni, Wnj);
    edge_mma<<<444, 256, k2_smem>>>(efeats, src, dst, Wfij, attn, bias, fout);

    // aggregation
    agg_kernel<<<(NN * 32 + 255) / 256, 256>>>(hout);
}

// round 12
// speedup vs baseline: 1.0300x; 1.0300x over previous
#include <cuda_runtime.h>
#include <cuda_bf16.h>
#include <math.h>
#include <stdint.h>

// ---------------- problem constants ----------------
#define NN     100000      // nodes
#define EE     1600000     // edges
#define NH     4           // heads
#define FN     32
#define FE     16
#define HFN    128         // NH*FN
#define HFE    64          // NH*FE

// ---------------- scratch (device globals) ----------------
__device__ float g_fni [NN * HFE];
__device__ float g_fnj [NN * HFE];
__device__ float g_h   [NN * HFN];
__device__ float g_eexp[EE * NH];      // CSR (dst-sorted) order
__device__ int   g_cnt [NN];
__device__ int   g_rowoff[NN + 1];
__device__ int   g_bsum[128];
__device__ int   g_ipos[EE];           // original edge id -> CSR position
__device__ int   g_psrc[EE];           // src in CSR order

// ================= helpers =================
__device__ __forceinline__ uint32_t smem_u32(const void* p) {
    uint32_t r;
    asm("{ .reg .u64 t; cvta.to.shared.u64 t, %1; cvt.u32.u64 %0, t; }"
        : "=r"(r) : "l"(p));
    return r;
}
// cutlass Swizzle<3,4,3>: conflict-free ldmatrix on 128B-row atoms
#define SWZ(x) ((x) ^ (((x) >> 3) & 0x70))

#define LDSM4(r0, r1, r2, r3, a) \
    asm volatile("ldmatrix.sync.aligned.m8n8.x4.shared.b16 {%0,%1,%2,%3}, [%4];" \
                 : "=r"(r0), "=r"(r1), "=r"(r2), "=r"(r3) : "r"(a))

#define MMA16816(d, a, b0, b1) \
    asm volatile("mma.sync.aligned.m16n8k16.row.col.f32.bf16.bf16.f32 " \
                 "{%0,%1,%2,%3},{%4,%5,%6,%7},{%8,%9},{%0,%1,%2,%3};" \
                 : "+f"((d)[0]), "+f"((d)[1]), "+f"((d)[2]), "+f"((d)[3]) \
                 : "r"((a)[0]), "r"((a)[1]), "r"((a)[2]), "r"((a)[3]), \
                   "r"(b0), "r"(b1))

// packed bf16 two-term split of (x,y):
//   hi = {bf16(y) : bf16(x)}, lo = {bf16(y - hi_y) : bf16(x - hi_x)}
__device__ __forceinline__ void split2pack(float x, float y, uint32_t& hi, uint32_t& lo) {
    asm("cvt.rn.bf16x2.f32 %0, %1, %2;" : "=r"(hi) : "f"(y), "f"(x));
    float hx = __uint_as_float(hi << 16);
    float hy = __uint_as_float(hi & 0xFFFF0000u);
    float rx = x - hx;
    float ry = y - hy;
    asm("cvt.rn.bf16x2.f32 %0, %1, %2;" : "=r"(lo) : "f"(ry), "f"(rx));
}
// scalar split (weights staging only; negligible volume)
__device__ __forceinline__ void split_bf(float x, unsigned short& h, unsigned short& l) {
    __nv_bfloat16 bh = __float2bfloat16_rn(x);
    h = __bfloat16_as_ushort(bh);
    float r = x - __bfloat162float(bh);
    l = __bfloat16_as_ushort(__float2bfloat16_rn(r));
}

// ================= CSR build =================
__global__ void zero_cnt_kernel() {
    int i = blockIdx.x * blockDim.x + threadIdx.x;
    if (i < NN) g_cnt[i] = 0;
}
__global__ void deg_kernel(const int* __restrict__ dst) {
    int e = blockIdx.x * blockDim.x + threadIdx.x;
    if (e < EE) atomicAdd(&g_cnt[dst[e]], 1);
}

// multi-block scan: local block scans + block-sum scan + fixup
#define SCAN_B ((NN + 1023) / 1024)      // 98
__global__ void scan1_kernel() {
    __shared__ int wsums[32];
    int tid = threadIdx.x, lane = tid & 31, wid = tid >> 5;
    int i = blockIdx.x * 1024 + tid;
    int v = (i < NN) ? g_cnt[i] : 0;
    int x = v;
    #pragma unroll
    for (int o = 1; o < 32; o <<= 1) {
        int y = __shfl_up_sync(0xffffffffu, x, o);
        if (lane >= o) x += y;
    }
    if (lane == 31) wsums[wid] = x;
    __syncthreads();
    if (wid == 0) {
        int s = wsums[lane];
        #pragma unroll
        for (int o = 1; o < 32; o <<= 1) {
            int y = __shfl_up_sync(0xffffffffu, s, o);
            if (lane >= o) s += y;
        }
        wsums[lane] = s;
    }
    __syncthreads();
    int warp_off = (wid == 0) ? 0 : wsums[wid - 1];
    int incl = x + warp_off;
    if (i < NN) g_rowoff[i] = incl - v;        // local exclusive
    if (tid == 1023) g_bsum[blockIdx.x] = incl;
}
__global__ void scan2_kernel() {
    __shared__ int ws[4];
    int tid = threadIdx.x, lane = tid & 31, wid = tid >> 5;
    int v = (tid < SCAN_B) ? g_bsum[tid] : 0;
    int x = v;
    #pragma unroll
    for (int o = 1; o < 32; o <<= 1) {
        int y = __shfl_up_sync(0xffffffffu, x, o);
        if (lane >= o) x += y;
    }
    if (lane == 31) ws[wid] = x;
    __syncthreads();
    if (tid == 0) {
        int a = 0;
        #pragma unroll
        for (int k = 0; k < 4; k++) { int t = ws[k]; ws[k] = a; a += t; }
        g_rowoff[NN] = a;
    }
    __syncthreads();
    if (tid < SCAN_B) g_bsum[tid] = x - v + ws[wid];   // exclusive block offset
}
__global__ void scan3_kernel() {
    int i = blockIdx.x * 1024 + threadIdx.x;
    if (i < NN) {
        int r = g_rowoff[i] + g_bsum[blockIdx.x];
        g_rowoff[i] = r;
        g_cnt[i] = r;                       // scatter cursor
    }
}

__global__ void scatter_kernel(const int* __restrict__ src,
                               const int* __restrict__ dst) {
    int e = blockIdx.x * blockDim.x + threadIdx.x;
    if (e < EE) {
        int d = dst[e];
        int pos = atomicAdd(&g_cnt[d], 1);
        g_ipos[e] = pos;                   // sequential write in e
        g_psrc[pos] = src[e];
    }
}

// ================= K1: node projections (mma.sync bf16 3-split) =================
// D[128 rows, 256 cols] = A[128,128] @ W^T[256,128]
// cols 0..63 -> g_fni, 64..127 -> g_fnj, 128..255 -> g_h (+bias)
#define K1_TILES ((NN + 127) / 128)    // 782

__global__ void __launch_bounds__(512, 1)
node_proj_mma(const float* __restrict__ nfeats, const float* __restrict__ Wnode,
              const float* __restrict__ bnode, const float* __restrict__ Wni,
              const float* __restrict__ Wnj)
{
    extern __shared__ unsigned char dynbuf[];
    __shared__ float sbias[HFN];

    uint32_t du = smem_u32(dynbuf);
    uint32_t b0a = (du + 1023u) & ~1023u;
    unsigned char* dp = dynbuf + (b0a - du);
    const uint32_t A_HI = 0, A_LO = 32768, B_HI = 65536, B_LO = 131072;

    int tid = threadIdx.x, lane = tid & 31, wid = tid >> 5;
    int mwarp = wid & 3, nwarp = wid >> 2;
    int lm = lane >> 3, lr = lane & 7;

    if (tid < HFN) sbias[tid] = bnode[tid];

    // Stage fused weights [256 n x 128 k], bf16 hi/lo
    for (int idx = tid; idx < 256 * 128; idx += 512) {
        int n = idx & 255, k = idx >> 8;
        float w;
        if (n < 64)        w = Wni[k * 64 + n];
        else if (n < 128)  w = Wnj[k * 64 + (n - 64)];
        else               w = Wnode[k * 128 + (n - 128)];
        unsigned short h, l;
        split_bf(w, h, l);
        uint32_t off = (uint32_t)((n >> 3) + ((k >> 6) << 5)) * 1024u
                     + (uint32_t)(n & 7) * 128u + ((uint32_t)(k & 63) << 1);
        uint32_t so = SWZ(off);
        *(unsigned short*)(dp + B_HI + so) = h;
        *(unsigned short*)(dp + B_LO + so) = l;
    }

    const uint32_t saHI = b0a + A_HI, saLO = b0a + A_LO;
    const uint32_t sbHI = b0a + B_HI, sbLO = b0a + B_LO;

    for (int tile = blockIdx.x; tile < K1_TILES; tile += gridDim.x) {
        int n0 = tile * 128;
        __syncthreads();
        // stage A tile [128 x 128] fp32 -> bf16 hi/lo (packed cvt)
        #pragma unroll
        for (int j = 0; j < 8; j++) {
            int i = j * 512 + tid;          // float4 index 0..4095
            int row = i >> 5;
            int kg  = (i & 31) << 2;
            int n = n0 + row;
            float4 x = make_float4(0.f, 0.f, 0.f, 0.f);
            if (n < NN) x = *(const float4*)&nfeats[(size_t)n * 128 + kg];
            uint32_t h01, l01, h23, l23;
            split2pack(x.x, x.y, h01, l01);
            split2pack(x.z, x.w, h23, l23);
            uint32_t off = (uint32_t)((row >> 3) + ((kg >> 6) << 4)) * 1024u
                         + (uint32_t)(row & 7) * 128u + ((uint32_t)(kg & 63) << 1);
            uint32_t so = SWZ(off);
            *(uint2*)(dp + A_HI + so) = make_uint2(h01, h23);
            *(uint2*)(dp + A_LO + so) = make_uint2(l01, l23);
        }
        __syncthreads();

        float acc[2][8][4];
        #pragma unroll
        for (int mf = 0; mf < 2; mf++)
            #pragma unroll
            for (int nf = 0; nf < 8; nf++)
                #pragma unroll
                for (int q = 0; q < 4; q++) acc[mf][nf][q] = 0.f;

        #pragma unroll
        for (int term = 0; term < 3; term++) {
            uint32_t abase = (term == 2) ? saLO : saHI;
            uint32_t bbase = (term == 1) ? sbLO : sbHI;
            #pragma unroll
            for (int ks = 0; ks < 8; ks++) {
                int k0 = ks * 16;
                uint32_t a[2][4];
                #pragma unroll
                for (int mf = 0; mf < 2; mf++) {
                    int row = mwarp * 32 + mf * 16 + ((lm & 1) << 3) + lr;
                    int kk  = k0 + ((lm >> 1) << 3);
                    uint32_t off = (uint32_t)((row >> 3) + ((kk >> 6) << 4)) * 1024u
                                 + (uint32_t)(row & 7) * 128u + ((uint32_t)(kk & 63) << 1);
                    LDSM4(a[mf][0], a[mf][1], a[mf][2], a[mf][3], abase + SWZ(off));
                }
                uint32_t b[4][4];
                #pragma unroll
                for (int p = 0; p < 4; p++) {
                    int n  = nwarp * 64 + p * 16 + ((lm >> 1) << 3) + lr;
                    int kk = k0 + ((lm & 1) << 3);
                    uint32_t off = (uint32_t)((n >> 3) + ((kk >> 6) << 5)) * 1024u
                                 + (uint32_t)(n & 7) * 128u + ((uint32_t)(kk & 63) << 1);
                    LDSM4(b[p][0], b[p][1], b[p][2], b[p][3], bbase + SWZ(off));
                }
                #pragma unroll
                for (int mf = 0; mf < 2; mf++)
                    #pragma unroll
                    for (int nf = 0; nf < 8; nf++)
                        MMA16816(acc[mf][nf], a[mf],
                                 b[nf >> 1][(nf & 1) * 2], b[nf >> 1][(nf & 1) * 2 + 1]);
            }
        }

        // fragment-layout epilogue
        int rb = n0 + mwarp * 32 + (lane >> 2);
        int cq = (lane & 3) * 2;
        #pragma unroll
        for (int mf = 0; mf < 2; mf++) {
            int r1 = rb + mf * 16, r2 = r1 + 8;
            #pragma unroll
            for (int nf = 0; nf < 8; nf++) {
                int cc = nf * 8 + cq;
                float* a4 = acc[mf][nf];
                float2 v1 = make_float2(a4[0], a4[1]);
                float2 v2 = make_float2(a4[2], a4[3]);
                if (nwarp == 0) {
                    if (r1 < NN) *(float2*)&g_fni[(size_t)r1 * 64 + cc] = v1;
                    if (r2 < NN) *(float2*)&g_fni[(size_t)r2 * 64 + cc] = v2;
                } else if (nwarp == 1) {
                    if (r1 < NN) *(float2*)&g_fnj[(size_t)r1 * 64 + cc] = v1;
                    if (r2 < NN) *(float2*)&g_fnj[(size_t)r2 * 64 + cc] = v2;
                } else {
                    int c2 = (nwarp - 2) * 64 + cc;
                    float b0f = sbias[c2], b1f = sbias[c2 + 1];
                    v1.x += b0f; v1.y += b1f;
                    v2.x += b0f; v2.y += b1f;
                    if (r1 < NN) *(float2*)&g_h[(size_t)r1 * 128 + c2] = v1;
                    if (r2 < NN) *(float2*)&g_h[(size_t)r2 * 128 + c2] = v2;
                }
            }
        }
    }
}

// ================= K2: fused edge kernel (R8 form; eexp scattered to CSR pos) =
#define K2_TILES (EE / 128)            // 12500, exact
#define DPITCH   68

__global__ void __launch_bounds__(256, 2)
edge_mma(const float* __restrict__ efeats, const int* __restrict__ src,
         const int* __restrict__ dst, const float* __restrict__ Wfij,
         const float* __restrict__ attn, const float* __restrict__ bias,
         float* __restrict__ fout)
{
    extern __shared__ unsigned char dynbuf[];
    __shared__ float sattn[HFE], sbias[HFE];

    uint32_t du = smem_u32(dynbuf);
    uint32_t b0a = (du + 1023u) & ~1023u;
    unsigned char* dp = dynbuf + (b0a - du);
    const uint32_t A_HI = 0, A_LO = 16384, B_HI = 32768, B_LO = 40960, D_OFF = 49152;
    float* sD = (float*)(dp + D_OFF);   // [128][DPITCH]

    int tid = threadIdx.x, lane = tid & 31, wid = tid >> 5;
    int mwarp = wid & 3, nwarp = wid >> 2;
    int lm = lane >> 3, lr = lane & 7;

    if (tid < HFE) { sattn[tid] = attn[tid]; sbias[tid] = bias[tid]; }

    // Stage Wfij as [n=64][k=64], bf16 hi/lo
    for (int idx = tid; idx < 64 * 64; idx += 256) {
        int n = idx & 63, k = idx >> 6;
        unsigned short h, l;
        split_bf(Wfij[k * 64 + n], h, l);
        uint32_t off = (uint32_t)(n >> 3) * 1024u + (uint32_t)(n & 7) * 128u
                     + ((uint32_t)k << 1);
        uint32_t so = SWZ(off);
        *(unsigned short*)(dp + B_HI + so) = h;
        *(unsigned short*)(dp + B_LO + so) = l;
    }

    const uint32_t saHI = b0a + A_HI, saLO = b0a + A_LO;
    const uint32_t sbHI = b0a + B_HI, sbLO = b0a + B_LO;

    for (int tile = blockIdx.x; tile < K2_TILES; tile += gridDim.x) {
        int e0 = tile * 128;
        __syncthreads();
        // stage A tile [128 edges x 64 feats] fp32 -> bf16 hi/lo (packed cvt)
        #pragma unroll
        for (int j = 0; j < 8; j++) {
            int i = j * 256 + tid;          // float4 index 0..2047
            int row = i >> 4;
            int kg  = (i & 15) << 2;
            float4 x = *(const float4*)&efeats[(size_t)(e0 + row) * 64 + kg];
            uint32_t h01, l01, h23, l23;
            split2pack(x.x, x.y, h01, l01);
            split2pack(x.z, x.w, h23, l23);
            uint32_t off = (uint32_t)(row >> 3) * 1024u + (uint32_t)(row & 7) * 128u
                         + ((uint32_t)kg << 1);
            uint32_t so = SWZ(off);
            *(uint2*)(dp + A_HI + so) = make_uint2(h01, h23);
            *(uint2*)(dp + A_LO + so) = make_uint2(l01, l23);
        }
        __syncthreads();

        float acc[2][4][4];
        #pragma unroll
        for (int mf = 0; mf < 2; mf++)
            #pragma unroll
            for (int nf = 0; nf < 4; nf++)
                #pragma unroll
                for (int q = 0; q < 4; q++) acc[mf][nf][q] = 0.f;

        #pragma unroll
        for (int term = 0; term < 3; term++) {
            uint32_t abase = (term == 2) ? saLO : saHI;
            uint32_t bbase = (term == 1) ? sbLO : sbHI;
            #pragma unroll
            for (int ks = 0; ks < 4; ks++) {
                int k0 = ks * 16;
                uint32_t a[2][4];
                #pragma unroll
                for (int mf = 0; mf < 2; mf++) {
                    int row = mwarp * 32 + mf * 16 + ((lm & 1) << 3) + lr;
                    int kk  = k0 + ((lm >> 1) << 3);
                    uint32_t off = (uint32_t)(row >> 3) * 1024u
                                 + (uint32_t)(row & 7) * 128u + ((uint32_t)kk << 1);
                    LDSM4(a[mf][0], a[mf][1], a[mf][2], a[mf][3], abase + SWZ(off));
                }
                uint32_t b[2][4];
                #pragma unroll
                for (int p = 0; p < 2; p++) {
                    int n  = nwarp * 32 + p * 16 + ((lm >> 1) << 3) + lr;
                    int kk = k0 + ((lm & 1) << 3);
                    uint32_t off = (uint32_t)(n >> 3) * 1024u
                                 + (uint32_t)(n & 7) * 128u + ((uint32_t)kk << 1);
                    LDSM4(b[p][0], b[p][1], b[p][2], b[p][3], bbase + SWZ(off));
                }
                #pragma unroll
                for (int mf = 0; mf < 2; mf++)
                    #pragma unroll
                    for (int nf = 0; nf < 4; nf++)
                        MMA16816(acc[mf][nf], a[mf],
                                 b[nf >> 1][(nf & 1) * 2], b[nf >> 1][(nf & 1) * 2 + 1]);
            }
        }

        // accumulators -> smem D
        {
            int rb = mwarp * 32 + (lane >> 2);
            int cq = (lane & 3) * 2;
            #pragma unroll
            for (int mf = 0; mf < 2; mf++) {
                int r1 = rb + mf * 16, r2 = r1 + 8;
                #pragma unroll
                for (int nf = 0; nf < 4; nf++) {
                    int cc = nwarp * 32 + nf * 8 + cq;
                    float* a4 = acc[mf][nf];
                    *(float2*)&sD[r1 * DPITCH + cc] = make_float2(a4[0], a4[1]);
                    *(float2*)&sD[r2 * DPITCH + cc] = make_float2(a4[2], a4[3]);
                }
            }
        }
        __syncthreads();

        // per-edge epilogue: 2 threads per edge, 32 cols (2 heads) each
        int eloc = tid >> 1;
        int half = tid & 1;
        int e = e0 + eloc;
        int sn = src[e], dn = dst[e];
        int ip = g_ipos[e];                // CSR position for eexp write
        const float* fni = &g_fni[(size_t)sn * 64 + half * 32];
        const float* fnj = &g_fnj[(size_t)dn * 64 + half * 32];
        float* fo = &fout[(size_t)e * 64 + half * 32];
        const float* dsm = &sD[eloc * DPITCH + half * 32];
        float p0 = 0.f, p1 = 0.f;
        #pragma unroll
        for (int g = 0; g < 8; g++) {
            int c = g * 4;
            float4 dd = *(const float4*)&dsm[c];
            float4 a4 = *(const float4*)&fni[c];
            float4 b4 = *(const float4*)&fnj[c];
            int cb = half * 32 + c;
            float4 o;
            o.x = dd.x + a4.x + b4.x + sbias[cb + 0];
            o.y = dd.y + a4.y + b4.y + sbias[cb + 1];
            o.z = dd.z + a4.z + b4.z + sbias[cb + 2];
            o.w = dd.w + a4.w + b4.w + sbias[cb + 3];
            o.x = (o.x > 0.f) ? o.x : 0.01f * o.x;
            o.y = (o.y > 0.f) ? o.y : 0.01f * o.y;
            o.z = (o.z > 0.f) ? o.z : 0.01f * o.z;
            o.w = (o.w > 0.f) ? o.w : 0.01f * o.w;
            float ph = o.x * sattn[cb + 0] + o.y * sattn[cb + 1]
                     + o.z * sattn[cb + 2] + o.w * sattn[cb + 3];
            if (g < 4) p0 += ph; else p1 += ph;
            *(float4*)&fo[c] = o;
        }
        // unnormalized softmax numerators, scattered to CSR position so the
        // aggregation kernel reads eexp sequentially
        *(float2*)&g_eexp[(size_t)ip * 4 + half * 2] =
            make_float2(expf(p0), expf(p1));
    }
}

// ================= K3: per-node aggregation (warp per node, 2x unroll) =======
// eexp + psrc both sequential in CSR order; only g_h is gathered.
__global__ void __launch_bounds__(256)
agg_kernel(float* __restrict__ hout)
{
    int warp = (blockIdx.x * blockDim.x + threadIdx.x) >> 5;
    int lane = threadIdx.x & 31;
    if (warp >= NN) return;

    int beg = g_rowoff[warp];
    int end = g_rowoff[warp + 1];

    float a0 = 0.f, a1 = 0.f, a2 = 0.f, a3 = 0.f;
    float s0 = 0.f, s1 = 0.f, s2 = 0.f, s3 = 0.f;

    int i = beg;
    for (; i + 2 <= end; i += 2) {
        int sA = g_psrc[i], sB = g_psrc[i + 1];
        float4 exA = *(float4*)&g_eexp[(size_t)i * 4];
        float4 exB = *(float4*)&g_eexp[(size_t)(i + 1) * 4];
        const float* hA = &g_h[(size_t)sA * 128];
        const float* hB = &g_h[(size_t)sB * 128];
        float vA0 = hA[lane],      vB0 = hB[lane];
        float vA1 = hA[32 + lane], vB1 = hB[32 + lane];
        float vA2 = hA[64 + lane], vB2 = hB[64 + lane];
        float vA3 = hA[96 + lane], vB3 = hB[96 + lane];
        a0 = fmaf(exA.x, vA0, a0); a0 = fmaf(exB.x, vB0, a0);
        a1 = fmaf(exA.y, vA1, a1); a1 = fmaf(exB.y, vB1, a1);
        a2 = fmaf(exA.z, vA2, a2); a2 = fmaf(exB.z, vB2, a2);
        a3 = fmaf(exA.w, vA3, a3); a3 = fmaf(exB.w, vB3, a3);
        s0 += exA.x + exB.x; s1 += exA.y + exB.y;
        s2 += exA.z + exB.z; s3 += exA.w + exB.w;
    }
    if (i < end) {
        int s = g_psrc[i];
        float4 ex = *(float4*)&g_eexp[(size_t)i * 4];
        const float* hp = &g_h[(size_t)s * 128];
        a0 = fmaf(ex.x, hp[lane],      a0);
        a1 = fmaf(ex.y, hp[32 + lane], a1);
        a2 = fmaf(ex.z, hp[64 + lane], a2);
        a3 = fmaf(ex.w, hp[96 + lane], a3);
        s0 += ex.x; s1 += ex.y; s2 += ex.z; s3 += ex.w;
    }

    float* op = &hout[(size_t)warp * 128];
    if (end > beg) {
        op[lane]      = a0 / s0;
        op[32 + lane] = a1 / s1;
        op[64 + lane] = a2 / s2;
        op[96 + lane] = a3 / s3;
    } else {
        op[lane] = 0.f; op[32 + lane] = 0.f;
        op[64 + lane] = 0.f; op[96 + lane] = 0.f;
    }
}

// ================= launch =================
extern "C" void kernel_launch(void* const* d_in, const int* in_sizes, int n_in,
                              void* d_out, int out_size)
{
    const float* nfeats = (const float*)d_in[0];
    const float* efeats = (const float*)d_in[1];
    const int*   src    = (const int*)  d_in[2];
    const int*   dst    = (const int*)  d_in[3];
    const float* Wnode  = (const float*)d_in[4];
    const float* bnode  = (const float*)d_in[5];
    const float* Wni    = (const float*)d_in[6];
    const float* Wnj    = (const float*)d_in[7];
    const float* Wfij   = (const float*)d_in[8];
    const float* attn   = (const float*)d_in[9];
    const float* bias   = (const float*)d_in[10];

    float* out  = (float*)d_out;
    float* hout = out;                          // [N*H, FN] = N*128 floats
    float* fout = out + (size_t)NN * HFN;       // [E*H, FE] = E*64 floats

    const int k1_smem = 192 * 1024 + 1024;                    // 197632
    const int k2_smem = 48 * 1024 + 128 * DPITCH * 4 + 1024;  // 85120
    cudaFuncSetAttribute(node_proj_mma,
                         cudaFuncAttributeMaxDynamicSharedMemorySize, k1_smem);
    cudaFuncSetAttribute(edge_mma,
                         cudaFuncAttributeMaxDynamicSharedMemorySize, k2_smem);

    // CSR build (multi-block scan)
    zero_cnt_kernel<<<(NN + 255) / 256, 256>>>();
    deg_kernel<<<(EE + 255) / 256, 256>>>(dst);
    scan1_kernel<<<SCAN_B, 1024>>>();
    scan2_kernel<<<1, 128>>>();
    scan3_kernel<<<SCAN_B, 1024>>>();
    scatter_kernel<<<(EE + 255) / 256, 256>>>(src, dst);

    // tensor-core projections + fused edge pass
    node_proj_mma<<<148, 512, k1_smem>>>(nfeats, Wnode, bnode, Wni, Wnj);
    edge_mma<<<296, 256, k2_smem>>>(efeats, src, dst, Wfij, attn, bias, fout);

    // aggregation
    agg_kernel<<<(NN * 32 + 255) / 256, 256>>>(hout);
}

// round 13
// speedup vs baseline: 1.0340x; 1.0038x over previous
#include <cuda_runtime.h>
#include <cuda_bf16.h>
#include <math.h>
#include <stdint.h>

// ---------------- problem constants ----------------
#define NN     100000      // nodes
#define EE     1600000     // edges
#define NH     4           // heads
#define FN     32
#define FE     16
#define HFN    128         // NH*FN
#define HFE    64          // NH*FE

// ---------------- scratch (device globals) ----------------
__device__ float g_fni [NN * HFE];
__device__ float g_fnj [NN * HFE];
__device__ float g_h   [NN * HFN];
__device__ float g_eexp[EE * NH];      // original edge order
__device__ int   g_cnt [NN];
__device__ int   g_rowoff[NN + 1];
__device__ int   g_bsum[128];
__device__ int   g_perm[EE];           // CSR position -> original edge id
__device__ int   g_psrc[EE];           // src in CSR order

// ================= helpers =================
__device__ __forceinline__ uint32_t smem_u32(const void* p) {
    uint32_t r;
    asm("{ .reg .u64 t; cvta.to.shared.u64 t, %1; cvt.u32.u64 %0, t; }"
        : "=r"(r) : "l"(p));
    return r;
}
// cutlass Swizzle<3,4,3>: conflict-free ldmatrix on 128B-row atoms
#define SWZ(x) ((x) ^ (((x) >> 3) & 0x70))

#define LDSM4(r0, r1, r2, r3, a) \
    asm volatile("ldmatrix.sync.aligned.m8n8.x4.shared.b16 {%0,%1,%2,%3}, [%4];" \
                 : "=r"(r0), "=r"(r1), "=r"(r2), "=r"(r3) : "r"(a))

#define MMA16816(d, a, b0, b1) \
    asm volatile("mma.sync.aligned.m16n8k16.row.col.f32.bf16.bf16.f32 " \
                 "{%0,%1,%2,%3},{%4,%5,%6,%7},{%8,%9},{%0,%1,%2,%3};" \
                 : "+f"((d)[0]), "+f"((d)[1]), "+f"((d)[2]), "+f"((d)[3]) \
                 : "r"((a)[0]), "r"((a)[1]), "r"((a)[2]), "r"((a)[3]), \
                   "r"(b0), "r"(b1))

// packed bf16 two-term split of (x,y):
//   hi = {bf16(y) : bf16(x)}, lo = {bf16(y - hi_y) : bf16(x - hi_x)}
__device__ __forceinline__ void split2pack(float x, float y, uint32_t& hi, uint32_t& lo) {
    asm("cvt.rn.bf16x2.f32 %0, %1, %2;" : "=r"(hi) : "f"(y), "f"(x));
    float hx = __uint_as_float(hi << 16);
    float hy = __uint_as_float(hi & 0xFFFF0000u);
    float rx = x - hx;
    float ry = y - hy;
    asm("cvt.rn.bf16x2.f32 %0, %1, %2;" : "=r"(lo) : "f"(ry), "f"(rx));
}
// scalar split (weights staging only; negligible volume)
__device__ __forceinline__ void split_bf(float x, unsigned short& h, unsigned short& l) {
    __nv_bfloat16 bh = __float2bfloat16_rn(x);
    h = __bfloat16_as_ushort(bh);
    float r = x - __bfloat162float(bh);
    l = __bfloat16_as_ushort(__float2bfloat16_rn(r));
}

// ================= CSR build =================
__global__ void zero_cnt_kernel() {
    int i = blockIdx.x * blockDim.x + threadIdx.x;
    if (i < NN) g_cnt[i] = 0;
}
__global__ void deg_kernel(const int* __restrict__ dst) {
    int e = blockIdx.x * blockDim.x + threadIdx.x;
    if (e < EE) atomicAdd(&g_cnt[dst[e]], 1);
}

// multi-block scan: local block scans + block-sum scan + fixup
#define SCAN_B ((NN + 1023) / 1024)      // 98
__global__ void scan1_kernel() {
    __shared__ int wsums[32];
    int tid = threadIdx.x, lane = tid & 31, wid = tid >> 5;
    int i = blockIdx.x * 1024 + tid;
    int v = (i < NN) ? g_cnt[i] : 0;
    int x = v;
    #pragma unroll
    for (int o = 1; o < 32; o <<= 1) {
        int y = __shfl_up_sync(0xffffffffu, x, o);
        if (lane >= o) x += y;
    }
    if (lane == 31) wsums[wid] = x;
    __syncthreads();
    if (wid == 0) {
        int s = wsums[lane];
        #pragma unroll
        for (int o = 1; o < 32; o <<= 1) {
            int y = __shfl_up_sync(0xffffffffu, s, o);
            if (lane >= o) s += y;
        }
        wsums[lane] = s;
    }
    __syncthreads();
    int warp_off = (wid == 0) ? 0 : wsums[wid - 1];
    int incl = x + warp_off;
    if (i < NN) g_rowoff[i] = incl - v;        // local exclusive
    if (tid == 1023) g_bsum[blockIdx.x] = incl;
}
__global__ void scan2_kernel() {
    __shared__ int ws[4];
    int tid = threadIdx.x, lane = tid & 31, wid = tid >> 5;
    int v = (tid < SCAN_B) ? g_bsum[tid] : 0;
    int x = v;
    #pragma unroll
    for (int o = 1; o < 32; o <<= 1) {
        int y = __shfl_up_sync(0xffffffffu, x, o);
        if (lane >= o) x += y;
    }
    if (lane == 31) ws[wid] = x;
    __syncthreads();
    if (tid == 0) {
        int a = 0;
        #pragma unroll
        for (int k = 0; k < 4; k++) { int t = ws[k]; ws[k] = a; a += t; }
        g_rowoff[NN] = a;
    }
    __syncthreads();
    if (tid < SCAN_B) g_bsum[tid] = x - v + ws[wid];   // exclusive block offset
}
__global__ void scan3_kernel() {
    int i = blockIdx.x * 1024 + threadIdx.x;
    if (i < NN) {
        int r = g_rowoff[i] + g_bsum[blockIdx.x];
        g_rowoff[i] = r;
        g_cnt[i] = r;                       // scatter cursor
    }
}

__global__ void scatter_kernel(const int* __restrict__ src,
                               const int* __restrict__ dst) {
    int e = blockIdx.x * blockDim.x + threadIdx.x;
    if (e < EE) {
        int d = dst[e];
        int pos = atomicAdd(&g_cnt[d], 1);
        g_perm[pos] = e;
        g_psrc[pos] = src[e];
    }
}

// ================= K1: node projections (mma.sync bf16 3-split) =================
// D[128 rows, 256 cols] = A[128,128] @ W^T[256,128]
// cols 0..63 -> g_fni, 64..127 -> g_fnj, 128..255 -> g_h (+bias)
#define K1_TILES ((NN + 127) / 128)    // 782

__global__ void __launch_bounds__(512, 1)
node_proj_mma(const float* __restrict__ nfeats, const float* __restrict__ Wnode,
              const float* __restrict__ bnode, const float* __restrict__ Wni,
              const float* __restrict__ Wnj)
{
    extern __shared__ unsigned char dynbuf[];
    __shared__ float sbias[HFN];

    uint32_t du = smem_u32(dynbuf);
    uint32_t b0a = (du + 1023u) & ~1023u;
    unsigned char* dp = dynbuf + (b0a - du);
    const uint32_t A_HI = 0, A_LO = 32768, B_HI = 65536, B_LO = 131072;

    int tid = threadIdx.x, lane = tid & 31, wid = tid >> 5;
    int mwarp = wid & 3, nwarp = wid >> 2;
    int lm = lane >> 3, lr = lane & 7;

    if (tid < HFN) sbias[tid] = bnode[tid];

    // Stage fused weights [256 n x 128 k], bf16 hi/lo
    for (int idx = tid; idx < 256 * 128; idx += 512) {
        int n = idx & 255, k = idx >> 8;
        float w;
        if (n < 64)        w = Wni[k * 64 + n];
        else if (n < 128)  w = Wnj[k * 64 + (n - 64)];
        else               w = Wnode[k * 128 + (n - 128)];
        unsigned short h, l;
        split_bf(w, h, l);
        uint32_t off = (uint32_t)((n >> 3) + ((k >> 6) << 5)) * 1024u
                     + (uint32_t)(n & 7) * 128u + ((uint32_t)(k & 63) << 1);
        uint32_t so = SWZ(off);
        *(unsigned short*)(dp + B_HI + so) = h;
        *(unsigned short*)(dp + B_LO + so) = l;
    }

    const uint32_t saHI = b0a + A_HI, saLO = b0a + A_LO;
    const uint32_t sbHI = b0a + B_HI, sbLO = b0a + B_LO;

    for (int tile = blockIdx.x; tile < K1_TILES; tile += gridDim.x) {
        int n0 = tile * 128;
        __syncthreads();
        // stage A tile [128 x 128] fp32 -> bf16 hi/lo (packed cvt)
        #pragma unroll
        for (int j = 0; j < 8; j++) {
            int i = j * 512 + tid;          // float4 index 0..4095
            int row = i >> 5;
            int kg  = (i & 31) << 2;
            int n = n0 + row;
            float4 x = make_float4(0.f, 0.f, 0.f, 0.f);
            if (n < NN) x = *(const float4*)&nfeats[(size_t)n * 128 + kg];
            uint32_t h01, l01, h23, l23;
            split2pack(x.x, x.y, h01, l01);
            split2pack(x.z, x.w, h23, l23);
            uint32_t off = (uint32_t)((row >> 3) + ((kg >> 6) << 4)) * 1024u
                         + (uint32_t)(row & 7) * 128u + ((uint32_t)(kg & 63) << 1);
            uint32_t so = SWZ(off);
            *(uint2*)(dp + A_HI + so) = make_uint2(h01, h23);
            *(uint2*)(dp + A_LO + so) = make_uint2(l01, l23);
        }
        __syncthreads();

        float acc[2][8][4];
        #pragma unroll
        for (int mf = 0; mf < 2; mf++)
            #pragma unroll
            for (int nf = 0; nf < 8; nf++)
                #pragma unroll
                for (int q = 0; q < 4; q++) acc[mf][nf][q] = 0.f;

        #pragma unroll
        for (int term = 0; term < 3; term++) {
            uint32_t abase = (term == 2) ? saLO : saHI;
            uint32_t bbase = (term == 1) ? sbLO : sbHI;
            #pragma unroll
            for (int ks = 0; ks < 8; ks++) {
                int k0 = ks * 16;
                uint32_t a[2][4];
                #pragma unroll
                for (int mf = 0; mf < 2; mf++) {
                    int row = mwarp * 32 + mf * 16 + ((lm & 1) << 3) + lr;
                    int kk  = k0 + ((lm >> 1) << 3);
                    uint32_t off = (uint32_t)((row >> 3) + ((kk >> 6) << 4)) * 1024u
                                 + (uint32_t)(row & 7) * 128u + ((uint32_t)(kk & 63) << 1);
                    LDSM4(a[mf][0], a[mf][1], a[mf][2], a[mf][3], abase + SWZ(off));
                }
                uint32_t b[4][4];
                #pragma unroll
                for (int p = 0; p < 4; p++) {
                    int n  = nwarp * 64 + p * 16 + ((lm >> 1) << 3) + lr;
                    int kk = k0 + ((lm & 1) << 3);
                    uint32_t off = (uint32_t)((n >> 3) + ((kk >> 6) << 5)) * 1024u
                                 + (uint32_t)(n & 7) * 128u + ((uint32_t)(kk & 63) << 1);
                    LDSM4(b[p][0], b[p][1], b[p][2], b[p][3], bbase + SWZ(off));
                }
                #pragma unroll
                for (int mf = 0; mf < 2; mf++)
                    #pragma unroll
                    for (int nf = 0; nf < 8; nf++)
                        MMA16816(acc[mf][nf], a[mf],
                                 b[nf >> 1][(nf & 1) * 2], b[nf >> 1][(nf & 1) * 2 + 1]);
            }
        }

        // fragment-layout epilogue
        int rb = n0 + mwarp * 32 + (lane >> 2);
        int cq = (lane & 3) * 2;
        #pragma unroll
        for (int mf = 0; mf < 2; mf++) {
            int r1 = rb + mf * 16, r2 = r1 + 8;
            #pragma unroll
            for (int nf = 0; nf < 8; nf++) {
                int cc = nf * 8 + cq;
                float* a4 = acc[mf][nf];
                float2 v1 = make_float2(a4[0], a4[1]);
                float2 v2 = make_float2(a4[2], a4[3]);
                if (nwarp == 0) {
                    if (r1 < NN) *(float2*)&g_fni[(size_t)r1 * 64 + cc] = v1;
                    if (r2 < NN) *(float2*)&g_fni[(size_t)r2 * 64 + cc] = v2;
                } else if (nwarp == 1) {
                    if (r1 < NN) *(float2*)&g_fnj[(size_t)r1 * 64 + cc] = v1;
                    if (r2 < NN) *(float2*)&g_fnj[(size_t)r2 * 64 + cc] = v2;
                } else {
                    int c2 = (nwarp - 2) * 64 + cc;
                    float b0f = sbias[c2], b1f = sbias[c2 + 1];
                    v1.x += b0f; v1.y += b1f;
                    v2.x += b0f; v2.y += b1f;
                    if (r1 < NN) *(float2*)&g_h[(size_t)r1 * 128 + c2] = v1;
                    if (r2 < NN) *(float2*)&g_h[(size_t)r2 * 128 + c2] = v2;
                }
            }
        }
    }
}

// ================= K2: fused edge kernel (R8 form) =================
#define K2_TILES (EE / 128)            // 12500, exact
#define DPITCH   68

__global__ void __launch_bounds__(256, 2)
edge_mma(const float* __restrict__ efeats, const int* __restrict__ src,
         const int* __restrict__ dst, const float* __restrict__ Wfij,
         const float* __restrict__ attn, const float* __restrict__ bias,
         float* __restrict__ fout)
{
    extern __shared__ unsigned char dynbuf[];
    __shared__ float sattn[HFE], sbias[HFE];

    uint32_t du = smem_u32(dynbuf);
    uint32_t b0a = (du + 1023u) & ~1023u;
    unsigned char* dp = dynbuf + (b0a - du);
    const uint32_t A_HI = 0, A_LO = 16384, B_HI = 32768, B_LO = 40960, D_OFF = 49152;
    float* sD = (float*)(dp + D_OFF);   // [128][DPITCH]

    int tid = threadIdx.x, lane = tid & 31, wid = tid >> 5;
    int mwarp = wid & 3, nwarp = wid >> 2;
    int lm = lane >> 3, lr = lane & 7;

    if (tid < HFE) { sattn[tid] = attn[tid]; sbias[tid] = bias[tid]; }

    // Stage Wfij as [n=64][k=64], bf16 hi/lo
    for (int idx = tid; idx < 64 * 64; idx += 256) {
        int n = idx & 63, k = idx >> 6;
        unsigned short h, l;
        split_bf(Wfij[k * 64 + n], h, l);
        uint32_t off = (uint32_t)(n >> 3) * 1024u + (uint32_t)(n & 7) * 128u
                     + ((uint32_t)k << 1);
        uint32_t so = SWZ(off);
        *(unsigned short*)(dp + B_HI + so) = h;
        *(unsigned short*)(dp + B_LO + so) = l;
    }

    const uint32_t saHI = b0a + A_HI, saLO = b0a + A_LO;
    const uint32_t sbHI = b0a + B_HI, sbLO = b0a + B_LO;

    for (int tile = blockIdx.x; tile < K2_TILES; tile += gridDim.x) {
        int e0 = tile * 128;
        __syncthreads();
        // stage A tile [128 edges x 64 feats] fp32 -> bf16 hi/lo (packed cvt)
        #pragma unroll
        for (int j = 0; j < 8; j++) {
            int i = j * 256 + tid;          // float4 index 0..2047
            int row = i >> 4;
            int kg  = (i & 15) << 2;
            float4 x = *(const float4*)&efeats[(size_t)(e0 + row) * 64 + kg];
            uint32_t h01, l01, h23, l23;
            split2pack(x.x, x.y, h01, l01);
            split2pack(x.z, x.w, h23, l23);
            uint32_t off = (uint32_t)(row >> 3) * 1024u + (uint32_t)(row & 7) * 128u
                         + ((uint32_t)kg << 1);
            uint32_t so = SWZ(off);
            *(uint2*)(dp + A_HI + so) = make_uint2(h01, h23);
            *(uint2*)(dp + A_LO + so) = make_uint2(l01, l23);
        }
        __syncthreads();

        float acc[2][4][4];
        #pragma unroll
        for (int mf = 0; mf < 2; mf++)
            #pragma unroll
            for (int nf = 0; nf < 4; nf++)
                #pragma unroll
                for (int q = 0; q < 4; q++) acc[mf][nf][q] = 0.f;

        #pragma unroll
        for (int term = 0; term < 3; term++) {
            uint32_t abase = (term == 2) ? saLO : saHI;
            uint32_t bbase = (term == 1) ? sbLO : sbHI;
            #pragma unroll
            for (int ks = 0; ks < 4; ks++) {
                int k0 = ks * 16;
                uint32_t a[2][4];
                #pragma unroll
                for (int mf = 0; mf < 2; mf++) {
                    int row = mwarp * 32 + mf * 16 + ((lm & 1) << 3) + lr;
                    int kk  = k0 + ((lm >> 1) << 3);
                    uint32_t off = (uint32_t)(row >> 3) * 1024u
                                 + (uint32_t)(row & 7) * 128u + ((uint32_t)kk << 1);
                    LDSM4(a[mf][0], a[mf][1], a[mf][2], a[mf][3], abase + SWZ(off));
                }
                uint32_t b[2][4];
                #pragma unroll
                for (int p = 0; p < 2; p++) {
                    int n  = nwarp * 32 + p * 16 + ((lm >> 1) << 3) + lr;
                    int kk = k0 + ((lm & 1) << 3);
                    uint32_t off = (uint32_t)(n >> 3) * 1024u
                                 + (uint32_t)(n & 7) * 128u + ((uint32_t)kk << 1);
                    LDSM4(b[p][0], b[p][1], b[p][2], b[p][3], bbase + SWZ(off));
                }
                #pragma unroll
                for (int mf = 0; mf < 2; mf++)
                    #pragma unroll
                    for (int nf = 0; nf < 4; nf++)
                        MMA16816(acc[mf][nf], a[mf],
                                 b[nf >> 1][(nf & 1) * 2], b[nf >> 1][(nf & 1) * 2 + 1]);
            }
        }

        // accumulators -> smem D
        {
            int rb = mwarp * 32 + (lane >> 2);
            int cq = (lane & 3) * 2;
            #pragma unroll
            for (int mf = 0; mf < 2; mf++) {
                int r1 = rb + mf * 16, r2 = r1 + 8;
                #pragma unroll
                for (int nf = 0; nf < 4; nf++) {
                    int cc = nwarp * 32 + nf * 8 + cq;
                    float* a4 = acc[mf][nf];
                    *(float2*)&sD[r1 * DPITCH + cc] = make_float2(a4[0], a4[1]);
                    *(float2*)&sD[r2 * DPITCH + cc] = make_float2(a4[2], a4[3]);
                }
            }
        }
        __syncthreads();

        // per-edge epilogue: 2 threads per edge, 32 cols (2 heads) each
        int eloc = tid >> 1;
        int half = tid & 1;
        int e = e0 + eloc;
        int sn = src[e], dn = dst[e];
        const float* fni = &g_fni[(size_t)sn * 64 + half * 32];
        const float* fnj = &g_fnj[(size_t)dn * 64 + half * 32];
        float* fo = &fout[(size_t)e * 64 + half * 32];
        const float* dsm = &sD[eloc * DPITCH + half * 32];
        float p0 = 0.f, p1 = 0.f;
        #pragma unroll
        for (int g = 0; g < 8; g++) {
            int c = g * 4;
            float4 dd = *(const float4*)&dsm[c];
            float4 a4 = *(const float4*)&fni[c];
            float4 b4 = *(const float4*)&fnj[c];
            int cb = half * 32 + c;
            float4 o;
            o.x = dd.x + a4.x + b4.x + sbias[cb + 0];
            o.y = dd.y + a4.y + b4.y + sbias[cb + 1];
            o.z = dd.z + a4.z + b4.z + sbias[cb + 2];
            o.w = dd.w + a4.w + b4.w + sbias[cb + 3];
            o.x = (o.x > 0.f) ? o.x : 0.01f * o.x;
            o.y = (o.y > 0.f) ? o.y : 0.01f * o.y;
            o.z = (o.z > 0.f) ? o.z : 0.01f * o.z;
            o.w = (o.w > 0.f) ? o.w : 0.01f * o.w;
            float ph = o.x * sattn[cb + 0] + o.y * sattn[cb + 1]
                     + o.z * sattn[cb + 2] + o.w * sattn[cb + 3];
            if (g < 4) p0 += ph; else p1 += ph;
            *(float4*)&fo[c] = o;
        }
        // unnormalized softmax numerators (shift-invariance: segment-max skipped)
        *(float2*)&g_eexp[(size_t)e * 4 + half * 2] =
            make_float2(expf(p0), expf(p1));
    }
}

// ================= K3: per-node aggregation (warp per node, 2x unroll) =================
__global__ void __launch_bounds__(256)
agg_kernel(float* __restrict__ hout)
{
    int warp = (blockIdx.x * blockDim.x + threadIdx.x) >> 5;
    int lane = threadIdx.x & 31;
    if (warp >= NN) return;

    int beg = g_rowoff[warp];
    int end = g_rowoff[warp + 1];

    float a0 = 0.f, a1 = 0.f, a2 = 0.f, a3 = 0.f;
    float s0 = 0.f, s1 = 0.f, s2 = 0.f, s3 = 0.f;

    int i = beg;
    for (; i + 2 <= end; i += 2) {
        int eA = g_perm[i], eB = g_perm[i + 1];
        int sA = g_psrc[i], sB = g_psrc[i + 1];
        float4 exA = *(float4*)&g_eexp[(size_t)eA * 4];
        float4 exB = *(float4*)&g_eexp[(size_t)eB * 4];
        const float* hA = &g_h[(size_t)sA * 128];
        const float* hB = &g_h[(size_t)sB * 128];
        float vA0 = hA[lane],      vB0 = hB[lane];
        float vA1 = hA[32 + lane], vB1 = hB[32 + lane];
        float vA2 = hA[64 + lane], vB2 = hB[64 + lane];
        float vA3 = hA[96 + lane], vB3 = hB[96 + lane];
        a0 = fmaf(exA.x, vA0, a0); a0 = fmaf(exB.x, vB0, a0);
        a1 = fmaf(exA.y, vA1, a1); a1 = fmaf(exB.y, vB1, a1);
        a2 = fmaf(exA.z, vA2, a2); a2 = fmaf(exB.z, vB2, a2);
        a3 = fmaf(exA.w, vA3, a3); a3 = fmaf(exB.w, vB3, a3);
        s0 += exA.x + exB.x; s1 += exA.y + exB.y;
        s2 += exA.z + exB.z; s3 += exA.w + exB.w;
    }
    if (i < end) {
        int e = g_perm[i];
        int s = g_psrc[i];
        float4 ex = *(float4*)&g_eexp[(size_t)e * 4];
        const float* hp = &g_h[(size_t)s * 128];
        a0 = fmaf(ex.x, hp[lane],      a0);
        a1 = fmaf(ex.y, hp[32 + lane], a1);
        a2 = fmaf(ex.z, hp[64 + lane], a2);
        a3 = fmaf(ex.w, hp[96 + lane], a3);
        s0 += ex.x; s1 += ex.y; s2 += ex.z; s3 += ex.w;
    }

    float* op = &hout[(size_t)warp * 128];
    if (end > beg) {
        op[lane]      = a0 / s0;
        op[32 + lane] = a1 / s1;
        op[64 + lane] = a2 / s2;
        op[96 + lane] = a3 / s3;
    } else {
        op[lane] = 0.f; op[32 + lane] = 0.f;
        op[64 + lane] = 0.f; op[96 + lane] = 0.f;
    }
}

// ================= launch =================
// Launch order puts edge_mma at position 4 (the launch the ncu capture
// profiles) while preserving all dependencies:
//   K1 -> K2 (fni/fnj/h);  zero->deg->scan1->scan2->scan3->scatter -> agg;
//   K2, scatter -> agg.
extern "C" void kernel_launch(void* const* d_in, const int* in_sizes, int n_in,
                              void* d_out, int out_size)
{
    const float* nfeats = (const float*)d_in[0];
    const float* efeats = (const float*)d_in[1];
    const int*   src    = (const int*)  d_in[2];
    const int*   dst    = (const int*)  d_in[3];
    const float* Wnode  = (const float*)d_in[4];
    const float* bnode  = (const float*)d_in[5];
    const float* Wni    = (const float*)d_in[6];
    const float* Wnj    = (const float*)d_in[7];
    const float* Wfij   = (const float*)d_in[8];
    const float* attn   = (const float*)d_in[9];
    const float* bias   = (const float*)d_in[10];

    float* out  = (float*)d_out;
    float* hout = out;                          // [N*H, FN] = N*128 floats
    float* fout = out + (size_t)NN * HFN;       // [E*H, FE] = E*64 floats

    const int k1_smem = 192 * 1024 + 1024;                    // 197632
    const int k2_smem = 48 * 1024 + 128 * DPITCH * 4 + 1024;  // 85120
    cudaFuncSetAttribute(node_proj_mma,
                         cudaFuncAttributeMaxDynamicSharedMemorySize, k1_smem);
    cudaFuncSetAttribute(edge_mma,
                         cudaFuncAttributeMaxDynamicSharedMemorySize, k2_smem);

    // 1: node projections
    node_proj_mma<<<148, 512, k1_smem>>>(nfeats, Wnode, bnode, Wni, Wnj);
    // 2-3: CSR build prefix (independent of K1/K2)
    zero_cnt_kernel<<<(NN + 255) / 256, 256>>>();
    deg_kernel<<<(EE + 255) / 256, 256>>>(dst);
    // 4: fused edge pass  <-- profiled launch
    edge_mma<<<296, 256, k2_smem>>>(efeats, src, dst, Wfij, attn, bias, fout);
    // 5-8: rest of CSR build
    scan1_kernel<<<SCAN_B, 1024>>>();
    scan2_kernel<<<1, 128>>>();
    scan3_kernel<<<SCAN_B, 1024>>>();
    scatter_kernel<<<(EE + 255) / 256, 256>>>(src, dst);
    // 9: aggregation
    agg_kernel<<<(NN * 32 + 255) / 256, 256>>>(hout);
}

// round 14
// speedup vs baseline: 1.4081x; 1.3619x over previous
#include <cuda_runtime.h>
#include <cuda_bf16.h>
#include <math.h>
#include <stdint.h>

// ---------------- problem constants ----------------
#define NN     100000      // nodes
#define EE     1600000     // edges
#define NH     4           // heads
#define FN     32
#define FE     16
#define HFN    128         // NH*FN
#define HFE    64          // NH*FE

// ---------------- scratch (device globals) ----------------
__device__ float g_fni [NN * HFE];
__device__ float g_fnj [NN * HFE];
__device__ float g_h   [NN * HFN];
__device__ float g_eexp[EE * NH];      // original edge order
__device__ int   g_cnt [NN];
__device__ int   g_rowoff[NN + 1];
__device__ int   g_bsum[128];
__device__ int   g_perm[EE];           // CSR position -> original edge id
__device__ int   g_psrc[EE];           // src in CSR order

// ================= helpers =================
__device__ __forceinline__ uint32_t smem_u32(const void* p) {
    uint32_t r;
    asm("{ .reg .u64 t; cvta.to.shared.u64 t, %1; cvt.u32.u64 %0, t; }"
        : "=r"(r) : "l"(p));
    return r;
}
// cutlass Swizzle<3,4,3>: conflict-free ldmatrix on 128B-row atoms
#define SWZ(x) ((x) ^ (((x) >> 3) & 0x70))

#define LDSM4(r0, r1, r2, r3, a) \
    asm volatile("ldmatrix.sync.aligned.m8n8.x4.shared.b16 {%0,%1,%2,%3}, [%4];" \
                 : "=r"(r0), "=r"(r1), "=r"(r2), "=r"(r3) : "r"(a))

#define MMA16816(d, a, b0, b1) \
    asm volatile("mma.sync.aligned.m16n8k16.row.col.f32.bf16.bf16.f32 " \
                 "{%0,%1,%2,%3},{%4,%5,%6,%7},{%8,%9},{%0,%1,%2,%3};" \
                 : "+f"((d)[0]), "+f"((d)[1]), "+f"((d)[2]), "+f"((d)[3]) \
                 : "r"((a)[0]), "r"((a)[1]), "r"((a)[2]), "r"((a)[3]), \
                   "r"(b0), "r"(b1))

// packed bf16 two-term split of (x,y):
//   hi = {bf16(y) : bf16(x)}, lo = {bf16(y - hi_y) : bf16(x - hi_x)}
__device__ __forceinline__ void split2pack(float x, float y, uint32_t& hi, uint32_t& lo) {
    asm("cvt.rn.bf16x2.f32 %0, %1, %2;" : "=r"(hi) : "f"(y), "f"(x));
    float hx = __uint_as_float(hi << 16);
    float hy = __uint_as_float(hi & 0xFFFF0000u);
    float rx = x - hx;
    float ry = y - hy;
    asm("cvt.rn.bf16x2.f32 %0, %1, %2;" : "=r"(lo) : "f"(ry), "f"(rx));
}
// scalar split (weights staging only; negligible volume)
__device__ __forceinline__ void split_bf(float x, unsigned short& h, unsigned short& l) {
    __nv_bfloat16 bh = __float2bfloat16_rn(x);
    h = __bfloat16_as_ushort(bh);
    float r = x - __bfloat162float(bh);
    l = __bfloat16_as_ushort(__float2bfloat16_rn(r));
}

// ================= CSR build =================
__global__ void zero_cnt_kernel() {
    int i = blockIdx.x * blockDim.x + threadIdx.x;
    if (i < NN) g_cnt[i] = 0;
}
__global__ void deg_kernel(const int* __restrict__ dst) {
    int e = blockIdx.x * blockDim.x + threadIdx.x;
    if (e < EE) atomicAdd(&g_cnt[dst[e]], 1);
}

// multi-block scan: local block scans + block-sum scan + fixup
#define SCAN_B ((NN + 1023) / 1024)      // 98
__global__ void scan1_kernel() {
    __shared__ int wsums[32];
    int tid = threadIdx.x, lane = tid & 31, wid = tid >> 5;
    int i = blockIdx.x * 1024 + tid;
    int v = (i < NN) ? g_cnt[i] : 0;
    int x = v;
    #pragma unroll
    for (int o = 1; o < 32; o <<= 1) {
        int y = __shfl_up_sync(0xffffffffu, x, o);
        if (lane >= o) x += y;
    }
    if (lane == 31) wsums[wid] = x;
    __syncthreads();
    if (wid == 0) {
        int s = wsums[lane];
        #pragma unroll
        for (int o = 1; o < 32; o <<= 1) {
            int y = __shfl_up_sync(0xffffffffu, s, o);
            if (lane >= o) s += y;
        }
        wsums[lane] = s;
    }
    __syncthreads();
    int warp_off = (wid == 0) ? 0 : wsums[wid - 1];
    int incl = x + warp_off;
    if (i < NN) g_rowoff[i] = incl - v;        // local exclusive
    if (tid == 1023) g_bsum[blockIdx.x] = incl;
}
__global__ void scan2_kernel() {
    __shared__ int ws[4];
    int tid = threadIdx.x, lane = tid & 31, wid = tid >> 5;
    int v = (tid < SCAN_B) ? g_bsum[tid] : 0;
    int x = v;
    #pragma unroll
    for (int o = 1; o < 32; o <<= 1) {
        int y = __shfl_up_sync(0xffffffffu, x, o);
        if (lane >= o) x += y;
    }
    if (lane == 31) ws[wid] = x;
    __syncthreads();
    if (tid == 0) {
        int a = 0;
        #pragma unroll
        for (int k = 0; k < 4; k++) { int t = ws[k]; ws[k] = a; a += t; }
        g_rowoff[NN] = a;
    }
    __syncthreads();
    if (tid < SCAN_B) g_bsum[tid] = x - v + ws[wid];   // exclusive block offset
}
__global__ void scan3_kernel() {
    int i = blockIdx.x * 1024 + threadIdx.x;
    if (i < NN) {
        int r = g_rowoff[i] + g_bsum[blockIdx.x];
        g_rowoff[i] = r;
        g_cnt[i] = r;                       // scatter cursor
    }
}

__global__ void scatter_kernel(const int* __restrict__ src,
                               const int* __restrict__ dst) {
    int e = blockIdx.x * blockDim.x + threadIdx.x;
    if (e < EE) {
        int d = dst[e];
        int pos = atomicAdd(&g_cnt[d], 1);
        g_perm[pos] = e;
        g_psrc[pos] = src[e];
    }
}

// ================= K1: node projections (mma.sync bf16 3-split) =================
// D[128 rows, 256 cols] = A[128,128] @ W^T[256,128]
// cols 0..63 -> g_fni, 64..127 -> g_fnj, 128..255 -> g_h (+bias)
#define K1_TILES ((NN + 127) / 128)    // 782

__global__ void __launch_bounds__(512, 1)
node_proj_mma(const float* __restrict__ nfeats, const float* __restrict__ Wnode,
              const float* __restrict__ bnode, const float* __restrict__ Wni,
              const float* __restrict__ Wnj)
{
    extern __shared__ unsigned char dynbuf[];
    __shared__ float sbias[HFN];

    uint32_t du = smem_u32(dynbuf);
    uint32_t b0a = (du + 1023u) & ~1023u;
    unsigned char* dp = dynbuf + (b0a - du);
    const uint32_t A_HI = 0, A_LO = 32768, B_HI = 65536, B_LO = 131072;

    int tid = threadIdx.x, lane = tid & 31, wid = tid >> 5;
    int mwarp = wid & 3, nwarp = wid >> 2;
    int lm = lane >> 3, lr = lane & 7;

    if (tid < HFN) sbias[tid] = bnode[tid];

    // Stage fused weights [256 n x 128 k], bf16 hi/lo
    for (int idx = tid; idx < 256 * 128; idx += 512) {
        int n = idx & 255, k = idx >> 8;
        float w;
        if (n < 64)        w = Wni[k * 64 + n];
        else if (n < 128)  w = Wnj[k * 64 + (n - 64)];
        else               w = Wnode[k * 128 + (n - 128)];
        unsigned short h, l;
        split_bf(w, h, l);
        uint32_t off = (uint32_t)((n >> 3) + ((k >> 6) << 5)) * 1024u
                     + (uint32_t)(n & 7) * 128u + ((uint32_t)(k & 63) << 1);
        uint32_t so = SWZ(off);
        *(unsigned short*)(dp + B_HI + so) = h;
        *(unsigned short*)(dp + B_LO + so) = l;
    }

    const uint32_t saHI = b0a + A_HI, saLO = b0a + A_LO;
    const uint32_t sbHI = b0a + B_HI, sbLO = b0a + B_LO;

    for (int tile = blockIdx.x; tile < K1_TILES; tile += gridDim.x) {
        int n0 = tile * 128;
        __syncthreads();
        // stage A tile [128 x 128] fp32 -> bf16 hi/lo (packed cvt)
        #pragma unroll
        for (int j = 0; j < 8; j++) {
            int i = j * 512 + tid;          // float4 index 0..4095
            int row = i >> 5;
            int kg  = (i & 31) << 2;
            int n = n0 + row;
            float4 x = make_float4(0.f, 0.f, 0.f, 0.f);
            if (n < NN) x = *(const float4*)&nfeats[(size_t)n * 128 + kg];
            uint32_t h01, l01, h23, l23;
            split2pack(x.x, x.y, h01, l01);
            split2pack(x.z, x.w, h23, l23);
            uint32_t off = (uint32_t)((row >> 3) + ((kg >> 6) << 4)) * 1024u
                         + (uint32_t)(row & 7) * 128u + ((uint32_t)(kg & 63) << 1);
            uint32_t so = SWZ(off);
            *(uint2*)(dp + A_HI + so) = make_uint2(h01, h23);
            *(uint2*)(dp + A_LO + so) = make_uint2(l01, l23);
        }
        __syncthreads();

        float acc[2][8][4];
        #pragma unroll
        for (int mf = 0; mf < 2; mf++)
            #pragma unroll
            for (int nf = 0; nf < 8; nf++)
                #pragma unroll
                for (int q = 0; q < 4; q++) acc[mf][nf][q] = 0.f;

        #pragma unroll
        for (int term = 0; term < 3; term++) {
            uint32_t abase = (term == 2) ? saLO : saHI;
            uint32_t bbase = (term == 1) ? sbLO : sbHI;
            #pragma unroll
            for (int ks = 0; ks < 8; ks++) {
                int k0 = ks * 16;
                uint32_t a[2][4];
                #pragma unroll
                for (int mf = 0; mf < 2; mf++) {
                    int row = mwarp * 32 + mf * 16 + ((lm & 1) << 3) + lr;
                    int kk  = k0 + ((lm >> 1) << 3);
                    uint32_t off = (uint32_t)((row >> 3) + ((kk >> 6) << 4)) * 1024u
                                 + (uint32_t)(row & 7) * 128u + ((uint32_t)(kk & 63) << 1);
                    LDSM4(a[mf][0], a[mf][1], a[mf][2], a[mf][3], abase + SWZ(off));
                }
                uint32_t b[4][4];
                #pragma unroll
                for (int p = 0; p < 4; p++) {
                    int n  = nwarp * 64 + p * 16 + ((lm >> 1) << 3) + lr;
                    int kk = k0 + ((lm & 1) << 3);
                    uint32_t off = (uint32_t)((n >> 3) + ((kk >> 6) << 5)) * 1024u
                                 + (uint32_t)(n & 7) * 128u + ((uint32_t)(kk & 63) << 1);
                    LDSM4(b[p][0], b[p][1], b[p][2], b[p][3], bbase + SWZ(off));
                }
                #pragma unroll
                for (int mf = 0; mf < 2; mf++)
                    #pragma unroll
                    for (int nf = 0; nf < 8; nf++)
                        MMA16816(acc[mf][nf], a[mf],
                                 b[nf >> 1][(nf & 1) * 2], b[nf >> 1][(nf & 1) * 2 + 1]);
            }
        }

        // fragment-layout epilogue
        int rb = n0 + mwarp * 32 + (lane >> 2);
        int cq = (lane & 3) * 2;
        #pragma unroll
        for (int mf = 0; mf < 2; mf++) {
            int r1 = rb + mf * 16, r2 = r1 + 8;
            #pragma unroll
            for (int nf = 0; nf < 8; nf++) {
                int cc = nf * 8 + cq;
                float* a4 = acc[mf][nf];
                float2 v1 = make_float2(a4[0], a4[1]);
                float2 v2 = make_float2(a4[2], a4[3]);
                if (nwarp == 0) {
                    if (r1 < NN) *(float2*)&g_fni[(size_t)r1 * 64 + cc] = v1;
                    if (r2 < NN) *(float2*)&g_fni[(size_t)r2 * 64 + cc] = v2;
                } else if (nwarp == 1) {
                    if (r1 < NN) *(float2*)&g_fnj[(size_t)r1 * 64 + cc] = v1;
                    if (r2 < NN) *(float2*)&g_fnj[(size_t)r2 * 64 + cc] = v2;
                } else {
                    int c2 = (nwarp - 2) * 64 + cc;
                    float b0f = sbias[c2], b1f = sbias[c2 + 1];
                    v1.x += b0f; v1.y += b1f;
                    v2.x += b0f; v2.y += b1f;
                    if (r1 < NN) *(float2*)&g_h[(size_t)r1 * 128 + c2] = v1;
                    if (r2 < NN) *(float2*)&g_h[(size_t)r2 * 128 + c2] = v2;
                }
            }
        }
    }
}

// ================= K2: fused edge kernel (coalesced quad epilogue) =================
// Epilogue mapping: 16 threads per edge, one float4 quad of the 64 cols each,
// 8 passes over the 128-edge tile. A warp covers 2 edges with 16 consecutive
// lanes per row -> gather/store instructions touch ~4 cache lines instead of
// 16-32 (L1-wavefront bound per R13 profile: L1=76.6%).
#define K2_TILES (EE / 128)            // 12500, exact
#define DPITCH   68

__global__ void __launch_bounds__(256, 2)
edge_mma(const float* __restrict__ efeats, const int* __restrict__ src,
         const int* __restrict__ dst, const float* __restrict__ Wfij,
         const float* __restrict__ attn, const float* __restrict__ bias,
         float* __restrict__ fout)
{
    extern __shared__ unsigned char dynbuf[];
    __shared__ float sattn[HFE], sbias[HFE];
    __shared__ int s_src[128], s_dst[128];

    uint32_t du = smem_u32(dynbuf);
    uint32_t b0a = (du + 1023u) & ~1023u;
    unsigned char* dp = dynbuf + (b0a - du);
    const uint32_t A_HI = 0, A_LO = 16384, B_HI = 32768, B_LO = 40960, D_OFF = 49152;
    float* sD = (float*)(dp + D_OFF);   // [128][DPITCH]

    int tid = threadIdx.x, lane = tid & 31, wid = tid >> 5;
    int mwarp = wid & 3, nwarp = wid >> 2;
    int lm = lane >> 3, lr = lane & 7;

    if (tid < HFE) { sattn[tid] = attn[tid]; sbias[tid] = bias[tid]; }

    // Stage Wfij as [n=64][k=64], bf16 hi/lo
    for (int idx = tid; idx < 64 * 64; idx += 256) {
        int n = idx & 63, k = idx >> 6;
        unsigned short h, l;
        split_bf(Wfij[k * 64 + n], h, l);
        uint32_t off = (uint32_t)(n >> 3) * 1024u + (uint32_t)(n & 7) * 128u
                     + ((uint32_t)k << 1);
        uint32_t so = SWZ(off);
        *(unsigned short*)(dp + B_HI + so) = h;
        *(unsigned short*)(dp + B_LO + so) = l;
    }

    const uint32_t saHI = b0a + A_HI, saLO = b0a + A_LO;
    const uint32_t sbHI = b0a + B_HI, sbLO = b0a + B_LO;

    // epilogue coordinates (fixed across tiles)
    int q    = tid & 15;               // quad 0..15, col = q*4
    int c    = q * 4;
    int head = q >> 2;                 // 0..3

    for (int tile = blockIdx.x; tile < K2_TILES; tile += gridDim.x) {
        int e0 = tile * 128;
        __syncthreads();
        // stage A tile + src/dst indices
        if (tid < 128)       s_src[tid]       = src[e0 + tid];
        else                 s_dst[tid - 128] = dst[e0 + tid - 128];
        #pragma unroll
        for (int j = 0; j < 8; j++) {
            int i = j * 256 + tid;          // float4 index 0..2047
            int row = i >> 4;
            int kg  = (i & 15) << 2;
            float4 x = *(const float4*)&efeats[(size_t)(e0 + row) * 64 + kg];
            uint32_t h01, l01, h23, l23;
            split2pack(x.x, x.y, h01, l01);
            split2pack(x.z, x.w, h23, l23);
            uint32_t off = (uint32_t)(row >> 3) * 1024u + (uint32_t)(row & 7) * 128u
                         + ((uint32_t)kg << 1);
            uint32_t so = SWZ(off);
            *(uint2*)(dp + A_HI + so) = make_uint2(h01, h23);
            *(uint2*)(dp + A_LO + so) = make_uint2(l01, l23);
        }
        __syncthreads();

        float acc[2][4][4];
        #pragma unroll
        for (int mf = 0; mf < 2; mf++)
            #pragma unroll
            for (int nf = 0; nf < 4; nf++)
                #pragma unroll
                for (int qq = 0; qq < 4; qq++) acc[mf][nf][qq] = 0.f;

        #pragma unroll
        for (int term = 0; term < 3; term++) {
            uint32_t abase = (term == 2) ? saLO : saHI;
            uint32_t bbase = (term == 1) ? sbLO : sbHI;
            #pragma unroll
            for (int ks = 0; ks < 4; ks++) {
                int k0 = ks * 16;
                uint32_t a[2][4];
                #pragma unroll
                for (int mf = 0; mf < 2; mf++) {
                    int row = mwarp * 32 + mf * 16 + ((lm & 1) << 3) + lr;
                    int kk  = k0 + ((lm >> 1) << 3);
                    uint32_t off = (uint32_t)(row >> 3) * 1024u
                                 + (uint32_t)(row & 7) * 128u + ((uint32_t)kk << 1);
                    LDSM4(a[mf][0], a[mf][1], a[mf][2], a[mf][3], abase + SWZ(off));
                }
                uint32_t b[2][4];
                #pragma unroll
                for (int p = 0; p < 2; p++) {
                    int n  = nwarp * 32 + p * 16 + ((lm >> 1) << 3) + lr;
                    int kk = k0 + ((lm & 1) << 3);
                    uint32_t off = (uint32_t)(n >> 3) * 1024u
                                 + (uint32_t)(n & 7) * 128u + ((uint32_t)kk << 1);
                    LDSM4(b[p][0], b[p][1], b[p][2], b[p][3], bbase + SWZ(off));
                }
                #pragma unroll
                for (int mf = 0; mf < 2; mf++)
                    #pragma unroll
                    for (int nf = 0; nf < 4; nf++)
                        MMA16816(acc[mf][nf], a[mf],
                                 b[nf >> 1][(nf & 1) * 2], b[nf >> 1][(nf & 1) * 2 + 1]);
            }
        }

        // accumulators -> smem D
        {
            int rb = mwarp * 32 + (lane >> 2);
            int cq = (lane & 3) * 2;
            #pragma unroll
            for (int mf = 0; mf < 2; mf++) {
                int r1 = rb + mf * 16, r2 = r1 + 8;
                #pragma unroll
                for (int nf = 0; nf < 4; nf++) {
                    int cc = nwarp * 32 + nf * 8 + cq;
                    float* a4 = acc[mf][nf];
                    *(float2*)&sD[r1 * DPITCH + cc] = make_float2(a4[0], a4[1]);
                    *(float2*)&sD[r2 * DPITCH + cc] = make_float2(a4[2], a4[3]);
                }
            }
        }
        __syncthreads();

        // coalesced per-edge epilogue: 16 threads/edge, 8 passes
        float b0f = sbias[c + 0], b1f = sbias[c + 1];
        float b2f = sbias[c + 2], b3f = sbias[c + 3];
        float t0f = sattn[c + 0], t1f = sattn[c + 1];
        float t2f = sattn[c + 2], t3f = sattn[c + 3];
        #pragma unroll
        for (int pass = 0; pass < 8; pass++) {
            int eloc = pass * 16 + (tid >> 4);
            int e = e0 + eloc;
            int sn = s_src[eloc], dn = s_dst[eloc];
            float4 dd = *(const float4*)&sD[eloc * DPITCH + c];
            float4 a4 = *(const float4*)&g_fni[(size_t)sn * 64 + c];
            float4 b4 = *(const float4*)&g_fnj[(size_t)dn * 64 + c];
            float4 o;
            o.x = dd.x + a4.x + b4.x + b0f;
            o.y = dd.y + a4.y + b4.y + b1f;
            o.z = dd.z + a4.z + b4.z + b2f;
            o.w = dd.w + a4.w + b4.w + b3f;
            o.x = (o.x > 0.f) ? o.x : 0.01f * o.x;
            o.y = (o.y > 0.f) ? o.y : 0.01f * o.y;
            o.z = (o.z > 0.f) ? o.z : 0.01f * o.z;
            o.w = (o.w > 0.f) ? o.w : 0.01f * o.w;
            *(float4*)&fout[(size_t)e * 64 + c] = o;
            float p = o.x * t0f + o.y * t1f + o.z * t2f + o.w * t3f;
            p += __shfl_xor_sync(0xffffffffu, p, 1);
            p += __shfl_xor_sync(0xffffffffu, p, 2);
            if ((tid & 3) == 0)
                g_eexp[(size_t)e * 4 + head] = expf(p);
        }
    }
}

// ================= K3: per-node aggregation (warp per node, 2x unroll) =================
__global__ void __launch_bounds__(256)
agg_kernel(float* __restrict__ hout)
{
    int warp = (blockIdx.x * blockDim.x + threadIdx.x) >> 5;
    int lane = threadIdx.x & 31;
    if (warp >= NN) return;

    int beg = g_rowoff[warp];
    int end = g_rowoff[warp + 1];

    float a0 = 0.f, a1 = 0.f, a2 = 0.f, a3 = 0.f;
    float s0 = 0.f, s1 = 0.f, s2 = 0.f, s3 = 0.f;

    int i = beg;
    for (; i + 2 <= end; i += 2) {
        int eA = g_perm[i], eB = g_perm[i + 1];
        int sA = g_psrc[i], sB = g_psrc[i + 1];
        float4 exA = *(float4*)&g_eexp[(size_t)eA * 4];
        float4 exB = *(float4*)&g_eexp[(size_t)eB * 4];
        const float* hA = &g_h[(size_t)sA * 128];
        const float* hB = &g_h[(size_t)sB * 128];
        float vA0 = hA[lane],      vB0 = hB[lane];
        float vA1 = hA[32 + lane], vB1 = hB[32 + lane];
        float vA2 = hA[64 + lane], vB2 = hB[64 + lane];
        float vA3 = hA[96 + lane], vB3 = hB[96 + lane];
        a0 = fmaf(exA.x, vA0, a0); a0 = fmaf(exB.x, vB0, a0);
        a1 = fmaf(exA.y, vA1, a1); a1 = fmaf(exB.y, vB1, a1);
        a2 = fmaf(exA.z, vA2, a2); a2 = fmaf(exB.z, vB2, a2);
        a3 = fmaf(exA.w, vA3, a3); a3 = fmaf(exB.w, vB3, a3);
        s0 += exA.x + exB.x; s1 += exA.y + exB.y;
        s2 += exA.z + exB.z; s3 += exA.w + exB.w;
    }
    if (i < end) {
        int e = g_perm[i];
        int s = g_psrc[i];
        float4 ex = *(float4*)&g_eexp[(size_t)e * 4];
        const float* hp = &g_h[(size_t)s * 128];
        a0 = fmaf(ex.x, hp[lane],      a0);
        a1 = fmaf(ex.y, hp[32 + lane], a1);
        a2 = fmaf(ex.z, hp[64 + lane], a2);
        a3 = fmaf(ex.w, hp[96 + lane], a3);
        s0 += ex.x; s1 += ex.y; s2 += ex.z; s3 += ex.w;
    }

    float* op = &hout[(size_t)warp * 128];
    if (end > beg) {
        op[lane]      = a0 / s0;
        op[32 + lane] = a1 / s1;
        op[64 + lane] = a2 / s2;
        op[96 + lane] = a3 / s3;
    } else {
        op[lane] = 0.f; op[32 + lane] = 0.f;
        op[64 + lane] = 0.f; op[96 + lane] = 0.f;
    }
}

// ================= launch =================
// edge_mma stays at position 4 (the launch the ncu capture profiles).
extern "C" void kernel_launch(void* const* d_in, const int* in_sizes, int n_in,
                              void* d_out, int out_size)
{
    const float* nfeats = (const float*)d_in[0];
    const float* efeats = (const float*)d_in[1];
    const int*   src    = (const int*)  d_in[2];
    const int*   dst    = (const int*)  d_in[3];
    const float* Wnode  = (const float*)d_in[4];
    const float* bnode  = (const float*)d_in[5];
    const float* Wni    = (const float*)d_in[6];
    const float* Wnj    = (const float*)d_in[7];
    const float* Wfij   = (const float*)d_in[8];
    const float* attn   = (const float*)d_in[9];
    const float* bias   = (const float*)d_in[10];

    float* out  = (float*)d_out;
    float* hout = out;                          // [N*H, FN] = N*128 floats
    float* fout = out + (size_t)NN * HFN;       // [E*H, FE] = E*64 floats

    const int k1_smem = 192 * 1024 + 1024;                    // 197632
    const int k2_smem = 48 * 1024 + 128 * DPITCH * 4 + 1024;  // 85120
    cudaFuncSetAttribute(node_proj_mma,
                         cudaFuncAttributeMaxDynamicSharedMemorySize, k1_smem);
    cudaFuncSetAttribute(edge_mma,
                         cudaFuncAttributeMaxDynamicSharedMemorySize, k2_smem);

    // 1: node projections
    node_proj_mma<<<148, 512, k1_smem>>>(nfeats, Wnode, bnode, Wni, Wnj);
    // 2-3: CSR build prefix (independent of K1/K2)
    zero_cnt_kernel<<<(NN + 255) / 256, 256>>>();
    deg_kernel<<<(EE + 255) / 256, 256>>>(dst);
    // 4: fused edge pass  <-- profiled launch
    edge_mma<<<296, 256, k2_smem>>>(efeats, src, dst, Wfij, attn, bias, fout);
    // 5-8: rest of CSR build
    scan1_kernel<<<SCAN_B, 1024>>>();
    scan2_kernel<<<1, 128>>>();
    scan3_kernel<<<SCAN_B, 1024>>>();
    scatter_kernel<<<(EE + 255) / 256, 256>>>(src, dst);
    // 9: aggregation
    agg_kernel<<<(NN * 32 + 255) / 256, 256>>>(hout);
}